// round 12
// baseline (speedup 1.0000x reference)
#include <cuda_runtime.h>
#include <math_constants.h>
#include <math.h>

#define Bsz 2
#define Nn 1024
#define N1 1025
#define Dm 128
#define Hh 8
#define Dk 16
#define Dff 512
#define NBk 32
#define KNN 10
#define AW 33          // 33 x 32-bit words cover 1025 mask bits per row
#define EPSf 1e-5f
#define SCALEf 0.25f   // 1/sqrt(16)
#define PASTR 20       // split-K partial stride (floats), 16B-aligned

// ------------------------- persistent device scratch -------------------------
__device__ float    d_HG [Bsz*N1*Dm];     // state: rows 0..1023 = h, row 1024 = g
__device__ float    d_POOL[Bsz*Dm];
__device__ float    d_D2 [(size_t)Bsz*Nn*Nn];
__device__ unsigned d_ADJ[Bsz*N1*AW];
__device__ float    d_Q  [Bsz*Hh*N1*Dk];  // head-major: [b][h][n][dk]
__device__ float    d_Kb [Bsz*Hh*N1*Dk];
__device__ float    d_Vb [Bsz*Hh*N1*Dk];
__device__ float    d_CTX[Bsz*N1*Dm];
__device__ float    d_QE [Bsz*Hh*N1*NBk]; // head-major: [b][h][n][bucket]
__device__ float    d_Y  [Bsz*N1*Dm];
__device__ float    d_T1 [Bsz*N1*Dff];
__device__ float    d_T2 [Bsz*N1*Dm];
__device__ float    d_SA1[Bsz*Dm], d_SA2[Bsz*Dm];   // Y col sums / sumsq
__device__ float    d_SB1[Bsz*Dm], d_SB2[Bsz*Dm];   // T2 col sums / sumsq
__device__ float    d_PA [3*Bsz*N1*Hh*PASTR];       // split-K partials

// ------------------------- input embedding + state init ----------------------
__global__ void k_input(const float* __restrict__ coords, const float* __restrict__ inW,
                        const float* __restrict__ inb, const float* __restrict__ gnode)
{
    int gid = blockIdx.x*blockDim.x + threadIdx.x;
    if (gid < Bsz*Dm) d_POOL[gid] = 0.f;
    if (gid >= Bsz*N1*Dm) return;
    int d = gid % Dm;
    int n = (gid / Dm) % N1;
    int b = gid / (Dm*N1);
    float v;
    if (n < Nn) {
        float x = coords[(b*Nn+n)*2+0];
        float y = coords[(b*Nn+n)*2+1];
        v = x*inW[d*2+0] + y*inW[d*2+1] + inb[d];
    } else {
        v = gnode[d];
    }
    d_HG[gid] = v;
}

// ------------------------- layer-0 g update: g += mean(h) --------------------
__global__ void k_colmean()
{
    __shared__ float red[8][Dm];
    int b = blockIdx.x;
    int d = threadIdx.x & 127;
    int g = threadIdx.x >> 7;
    const float* base = d_HG + (size_t)b*N1*Dm;
    float s = 0.f;
    for (int n = g; n < Nn; n += 8) s += base[n*Dm + d];
    red[g][d] = s;
    __syncthreads();
    if (g == 0) {
        float t = 0.f;
        #pragma unroll
        for (int i = 0; i < 8; i++) t += red[i][d];
        d_HG[(size_t)b*N1*Dm + Nn*Dm + d] += t * (1.f/Nn);
    }
}

// ===================== PAR1: D2 (self-norms) + QKV + ADJ-init + stat-zero =====
// grid: [0,272) d2 tiles, [272,470) qkv, [470,983) adjacency rows. 256 threads.
__global__ void k_par1(const float* __restrict__ wq, const float* __restrict__ wk,
                       const float* __restrict__ wv)
{
    __shared__ __align__(16) float As[2][16][68];
    __shared__ __align__(16) float Bs[2][16][68];
    __shared__ float rsq[64], csq[64];
    int bx = blockIdx.x;
    int tid = threadIdx.x;

    if (bx < 272) {        // ---------- D2 symmetric tile ----------
        int b = bx / 136;
        int x = bx % 136, bi = 0;
        while (x >= 16 - bi) { x -= 16 - bi; bi++; }
        int bj = bi + x;
        const float* A = d_HG + (size_t)b*N1*Dm;
        int tr = tid >> 4, tc = tid & 15;
        int r0 = bi*64, c0 = bj*64;
        int lr = tid >> 2, lc = (tid & 3)*4;
        float rn = 0.f, cn = 0.f;
        float4 va = *(const float4*)(A + (size_t)(r0+lr)*Dm + lc);
        float4 vb = *(const float4*)(A + (size_t)(c0+lr)*Dm + lc);
        rn += va.x*va.x + va.y*va.y + va.z*va.z + va.w*va.w;
        cn += vb.x*vb.x + vb.y*vb.y + vb.z*vb.z + vb.w*vb.w;
        As[0][lc+0][lr]=va.x; As[0][lc+1][lr]=va.y; As[0][lc+2][lr]=va.z; As[0][lc+3][lr]=va.w;
        Bs[0][lc+0][lr]=vb.x; Bs[0][lc+1][lr]=vb.y; Bs[0][lc+2][lr]=vb.z; Bs[0][lc+3][lr]=vb.w;
        __syncthreads();
        float acc[4][4] = {};
        #pragma unroll
        for (int s = 0; s < 8; s++) {
            int cur = s & 1;
            if (s < 7) {
                va = *(const float4*)(A + (size_t)(r0+lr)*Dm + (s+1)*16 + lc);
                vb = *(const float4*)(A + (size_t)(c0+lr)*Dm + (s+1)*16 + lc);
                rn += va.x*va.x + va.y*va.y + va.z*va.z + va.w*va.w;
                cn += vb.x*vb.x + vb.y*vb.y + vb.z*vb.z + vb.w*vb.w;
            }
            #pragma unroll
            for (int k = 0; k < 16; k++) {
                float4 a4 = *(const float4*)&As[cur][k][tr*4];
                float4 b4 = *(const float4*)&Bs[cur][k][tc*4];
                float a[4] = {a4.x, a4.y, a4.z, a4.w};
                float bv[4] = {b4.x, b4.y, b4.z, b4.w};
                #pragma unroll
                for (int i = 0; i < 4; i++)
                    #pragma unroll
                    for (int j = 0; j < 4; j++) acc[i][j] += a[i]*bv[j];
            }
            if (s < 7) {
                int nxt = cur ^ 1;
                As[nxt][lc+0][lr]=va.x; As[nxt][lc+1][lr]=va.y; As[nxt][lc+2][lr]=va.z; As[nxt][lc+3][lr]=va.w;
                Bs[nxt][lc+0][lr]=vb.x; Bs[nxt][lc+1][lr]=vb.y; Bs[nxt][lc+2][lr]=vb.z; Bs[nxt][lc+3][lr]=vb.w;
                __syncthreads();
            }
        }
        rn += __shfl_xor_sync(0xffffffffu, rn, 1);
        rn += __shfl_xor_sync(0xffffffffu, rn, 2);
        cn += __shfl_xor_sync(0xffffffffu, cn, 1);
        cn += __shfl_xor_sync(0xffffffffu, cn, 2);
        if ((tid & 3) == 0) { rsq[lr] = rn; csq[lr] = cn; }
        __syncthreads();
        float vals[4][4];
        #pragma unroll
        for (int i = 0; i < 4; i++) {
            int r = r0 + tr*4 + i;
            float sqr = rsq[tr*4 + i];
            float* orow = d_D2 + ((size_t)b*Nn + r)*Nn + c0 + tc*4;
            float o[4];
            #pragma unroll
            for (int j = 0; j < 4; j++) {
                int c = c0 + tc*4 + j;
                float v = sqr + csq[tc*4 + j] - 2.f*acc[i][j];
                o[j] = (r == c) ? CUDART_INF_F : v;
                vals[i][j] = o[j];
            }
            *(float4*)orow = make_float4(o[0], o[1], o[2], o[3]);
        }
        if (bi != bj) {
            #pragma unroll
            for (int j = 0; j < 4; j++) {
                int c = c0 + tc*4 + j;
                float* orow = d_D2 + ((size_t)b*Nn + c)*Nn + r0 + tr*4;
                *(float4*)orow = make_float4(vals[0][j], vals[1][j], vals[2][j], vals[3][j]);
            }
        }
        return;
    }

    if (bx < 470) {        // ---------- QKV GEMM ----------
        int idx = bx - 272;
        int sel = idx / 66, rem = idx % 66;
        const float* Bm = (sel == 0) ? wq : (sel == 1) ? wk : wv;
        float* C = (sel == 0) ? d_Q : (sel == 1) ? d_Kb : d_Vb;
        const int M = Bsz*N1;
        int tr = tid >> 4, tc = tid & 15;
        int r0 = (rem >> 1)*64, c0 = (rem & 1)*64;
        int lr = tid >> 2, lc = (tid & 3)*4;
        int gr = r0 + lr, gc = c0 + lr;
        const float4 z4 = make_float4(0.f,0.f,0.f,0.f);
        float4 va = (gr < M) ? *(const float4*)(d_HG + (size_t)gr*Dm + lc) : z4;
        float4 vb = *(const float4*)(Bm + (size_t)gc*Dm + lc);
        As[0][lc+0][lr]=va.x; As[0][lc+1][lr]=va.y; As[0][lc+2][lr]=va.z; As[0][lc+3][lr]=va.w;
        Bs[0][lc+0][lr]=vb.x; Bs[0][lc+1][lr]=vb.y; Bs[0][lc+2][lr]=vb.z; Bs[0][lc+3][lr]=vb.w;
        __syncthreads();
        float acc[4][4] = {};
        #pragma unroll
        for (int s = 0; s < 8; s++) {
            int cur = s & 1;
            if (s < 7) {
                va = (gr < M) ? *(const float4*)(d_HG + (size_t)gr*Dm + (s+1)*16 + lc) : z4;
                vb = *(const float4*)(Bm + (size_t)gc*Dm + (s+1)*16 + lc);
            }
            #pragma unroll
            for (int k = 0; k < 16; k++) {
                float4 a4 = *(const float4*)&As[cur][k][tr*4];
                float4 b4 = *(const float4*)&Bs[cur][k][tc*4];
                float a[4] = {a4.x, a4.y, a4.z, a4.w};
                float bv[4] = {b4.x, b4.y, b4.z, b4.w};
                #pragma unroll
                for (int i = 0; i < 4; i++)
                    #pragma unroll
                    for (int j = 0; j < 4; j++) acc[i][j] += a[i]*bv[j];
            }
            if (s < 7) {
                int nxt = cur ^ 1;
                As[nxt][lc+0][lr]=va.x; As[nxt][lc+1][lr]=va.y; As[nxt][lc+2][lr]=va.z; As[nxt][lc+3][lr]=va.w;
                Bs[nxt][lc+0][lr]=vb.x; Bs[nxt][lc+1][lr]=vb.y; Bs[nxt][lc+2][lr]=vb.z; Bs[nxt][lc+3][lr]=vb.w;
                __syncthreads();
            }
        }
        int c = c0 + tc*4;
        int h  = c >> 4;
        int dk = c & 15;
        #pragma unroll
        for (int i = 0; i < 4; i++) {
            int r = r0 + tr*4 + i;
            if (r >= M) continue;
            int bb = (r >= N1) ? 1 : 0;
            int n  = r - bb*N1;
            *(float4*)(C + ((size_t)(bb*Hh + h)*N1 + n)*Dk + dk) =
                make_float4(acc[i][0], acc[i][1], acc[i][2], acc[i][3]);
        }
        return;
    }

    // ---------- adjacency base pattern (+ stat-buffer zeroing on bx==470) ----
    {
        if (bx == 470) {   // zero the per-column stat totals for this layer
            d_SA1[tid] = 0.f; d_SA2[tid] = 0.f;
            d_SB1[tid] = 0.f; d_SB2[tid] = 0.f;
        }
        int row = (bx - 470)*4 + (tid >> 6);
        int t = tid & 63;
        if (row >= Bsz*N1 || t >= AW) return;
        int i = row % N1;
        int w = t;
        unsigned bits = 0u;
        #pragma unroll 4
        for (int q = 0; q < 32; q++) {
            int m = w*32 + q;
            if (m > Nn) break;
            bool on;
            if (i == Nn || m == Nn || i == m || i == 0 || m == 0) on = true;
            else {
                int di = i - m; if (di < 0) di = -di;
                on = ((i >> 7) == (m >> 7)) && (di <= 11);   // hier adjacency
            }
            if (on) bits |= 1u << q;
        }
        d_ADJ[row*AW + w] = bits;
    }
}

// ===================== PAR2: topk (2 warps/row) + qe (8 rows/block) ===========
// grid: [0,512) topk (4 rows x 2 warps), [512,769) qe (8 rows/block). 256 thr.
__global__ void k_par2(const float* __restrict__ emb)
{
    int bx = blockIdx.x;
    int tid = threadIdx.x;
    if (bx < 512) {        // ---------- exact top-10 kNN, 2 warps/row ----------
        __shared__ unsigned candK[2][4][2];
        __shared__ int      candJ[2][4][2];
        int wid  = tid >> 5;           // 0..7
        int lane = tid & 31;
        int rw   = wid >> 1;           // row within block 0..3
        int w    = wid & 1;            // column half 0/1
        int rowg = bx*4 + rw;          // 0..2047
        int b = rowg >> 10, i = rowg & 1023;
        const float* row = d_D2 + (size_t)rowg*Nn + w*512;
        unsigned uv[16];
        #pragma unroll
        for (int t = 0; t < 16; t++) {
            unsigned u = __float_as_uint(row[t*32 + lane]);
            uv[t] = (u & 0x80000000u) ? ~u : (u | 0x80000000u);
        }
        unsigned* adjb = d_ADJ + (size_t)b*N1*AW;
        for (int r = 0; r < KNN; r++) {
            unsigned m0 = min(uv[0], uv[4]),  m1 = min(uv[1], uv[5]);
            unsigned m2 = min(uv[2], uv[6]),  m3 = min(uv[3], uv[7]);
            m0 = min(m0, min(uv[8],  uv[12]));
            m1 = min(m1, min(uv[9],  uv[13]));
            m2 = min(m2, min(uv[10], uv[14]));
            m3 = min(m3, min(uv[11], uv[15]));
            unsigned mm = min(min(m0, m1), min(m2, m3));
            #pragma unroll
            for (int o = 16; o; o >>= 1)
                mm = min(mm, __shfl_xor_sync(0xffffffffu, mm, o));
            int lj = 0x7FFFFFFF;
            #pragma unroll
            for (int t = 0; t < 16; t++)
                if (uv[t] == mm) { lj = w*512 + t*32 + lane; break; }
            #pragma unroll
            for (int o = 16; o; o >>= 1)
                lj = min(lj, __shfl_xor_sync(0xffffffffu, lj, o));
            int pb = r & 1;
            if (lane == 0) { candK[pb][rw][w] = mm; candJ[pb][rw][w] = lj; }
            __syncthreads();
            unsigned k0 = candK[pb][rw][0], k1 = candK[pb][rw][1];
            int j0 = candJ[pb][rw][0], j1 = candJ[pb][rw][1];
            int bj;
            if (k0 < k1 || (k0 == k1 && j0 < j1)) bj = j0; else bj = j1;
            if (w == (bj >> 9)) {               // owning half clears the slot
                int jl = bj - w*512;
                if (lane == (jl & 31)) uv[jl >> 5] = 0xFFFFFFFFu;
            }
            if (w == 0 && lane == 0) {
                atomicOr(&adjb[i*AW + (bj >> 5)], 1u << (bj & 31));
                atomicOr(&adjb[bj*AW + (i >> 5)], 1u << (i & 31));
            }
        }
        return;
    }
    // ---------- qe: 8 rows per block ----------
    __shared__ float qs[8][Dm];
    int r0 = (bx - 512)*8;             // first global row (b*N1+n)
    if (tid < 128) {
        int hh = tid >> 4, dk = tid & 15;
        #pragma unroll
        for (int r = 0; r < 8; r++) {
            int row = r0 + r;
            if (row >= Bsz*N1) break;
            int b = (row >= N1) ? 1 : 0;
            int n = row - b*N1;
            qs[r][tid] = d_Q[((size_t)(b*Hh + hh)*N1 + n)*Dk + dk];
        }
    }
    __syncthreads();
    int h = tid >> 5, kb = tid & 31;
    float e[16];
    const float* ep = emb + kb*Dm + h*Dk;
    #pragma unroll
    for (int d = 0; d < 16; d++) e[d] = ep[d];
    #pragma unroll
    for (int r = 0; r < 8; r++) {
        int row = r0 + r;
        if (row >= Bsz*N1) break;
        int b = (row >= N1) ? 1 : 0;
        int n = row - b*N1;
        const float* q = qs[r] + h*Dk;
        float s = 0.f;
        #pragma unroll
        for (int d = 0; d < 16; d++) s += q[d]*e[d];
        d_QE[((size_t)(b*Hh + h)*N1 + n)*NBk + kb] = s;
    }
}

// ------------ Wo GEMM: fused split-K combine + residual + Y col-stats --------
// Y = combine(PA)/CTX @ Wo^T + HG;  SA1/SA2 += column sums of Y.
__global__ void k_gemmC(const float* __restrict__ Bm, float* __restrict__ C)
{
    __shared__ __align__(16) float As[2][16][36];
    __shared__ __align__(16) float Bs[2][16][68];
    const int M = Bsz*N1;
    const int PST = Bsz*N1*Hh*PASTR;
    int tid = threadIdx.x;
    int tr = tid >> 4, tc = tid & 15;
    int r0 = blockIdx.y*32, c0 = blockIdx.x*64;
    int lr = tid >> 2;
    int lc = (tid & 3) * 4;
    bool aload = tid < 128;
    int ar = tid >> 2;
    int gr = r0 + ar, gc = c0 + lr;
    const float4 z4 = make_float4(0.f,0.f,0.f,0.f);
    bool valid = aload && gr < M;
    int abb = (gr >= N1) ? 1 : 0;
    int nn = gr - abb*N1;
    bool dense = (nn == 0) || (nn == Nn);
    size_t pbase = ((size_t)gr*Hh)*PASTR;
    auto fetchA = [&](int s) -> float4 {
        if (!valid) return z4;
        if (dense) return *(const float4*)(d_CTX + (size_t)gr*Dm + s*16 + lc);
        size_t pb = pbase + (size_t)s*PASTR;
        float4 p0 = *(const float4*)(d_PA + pb + lc);
        float4 p1 = *(const float4*)(d_PA + PST + pb + lc);
        float4 p2 = *(const float4*)(d_PA + 2*PST + pb + lc);
        float l = d_PA[pb+16] + d_PA[PST+pb+16] + d_PA[2*PST+pb+16];
        float inv = __fdividef(1.f, l);
        return make_float4((p0.x+p1.x+p2.x)*inv, (p0.y+p1.y+p2.y)*inv,
                           (p0.z+p1.z+p2.z)*inv, (p0.w+p1.w+p2.w)*inv);
    };
    float4 va = fetchA(0);
    float4 vb = *(const float4*)(Bm + (size_t)gc*Dm + lc);
    if (aload) {
        As[0][lc+0][ar]=va.x; As[0][lc+1][ar]=va.y; As[0][lc+2][ar]=va.z; As[0][lc+3][ar]=va.w;
    }
    Bs[0][lc+0][lr]=vb.x; Bs[0][lc+1][lr]=vb.y; Bs[0][lc+2][lr]=vb.z; Bs[0][lc+3][lr]=vb.w;
    __syncthreads();
    float acc[2][4] = {};
    #pragma unroll
    for (int s = 0; s < 8; s++) {
        int cur = s & 1;
        if (s < 7) {
            va = fetchA(s+1);
            vb = *(const float4*)(Bm + (size_t)gc*Dm + (s+1)*16 + lc);
        }
        #pragma unroll
        for (int k = 0; k < 16; k++) {
            float2 a2 = *(const float2*)&As[cur][k][tr*2];
            float4 b4 = *(const float4*)&Bs[cur][k][tc*4];
            acc[0][0] += a2.x*b4.x; acc[0][1] += a2.x*b4.y;
            acc[0][2] += a2.x*b4.z; acc[0][3] += a2.x*b4.w;
            acc[1][0] += a2.y*b4.x; acc[1][1] += a2.y*b4.y;
            acc[1][2] += a2.y*b4.z; acc[1][3] += a2.y*b4.w;
        }
        if (s < 7) {
            int nxt = cur ^ 1;
            if (aload) {
                As[nxt][lc+0][ar]=va.x; As[nxt][lc+1][ar]=va.y; As[nxt][lc+2][ar]=va.z; As[nxt][lc+3][ar]=va.w;
            }
            Bs[nxt][lc+0][lr]=vb.x; Bs[nxt][lc+1][lr]=vb.y; Bs[nxt][lc+2][lr]=vb.z; Bs[nxt][lc+3][lr]=vb.w;
            __syncthreads();
        }
    }
    int c = c0 + tc*4;
    #pragma unroll
    for (int i = 0; i < 2; i++) {
        int r = r0 + tr*2 + i;
        if (r >= M) continue;
        int bb = (r >= N1) ? 1 : 0;
        float4 rv = *(const float4*)(d_HG + (size_t)r*Dm + c);
        float4 v = make_float4(acc[i][0]+rv.x, acc[i][1]+rv.y, acc[i][2]+rv.z, acc[i][3]+rv.w);
        *(float4*)(C + (size_t)r*Dm + c) = v;
        atomicAdd(&d_SA1[bb*Dm + c+0], v.x); atomicAdd(&d_SA2[bb*Dm + c+0], v.x*v.x);
        atomicAdd(&d_SA1[bb*Dm + c+1], v.y); atomicAdd(&d_SA2[bb*Dm + c+1], v.y*v.y);
        atomicAdd(&d_SA1[bb*Dm + c+2], v.z); atomicAdd(&d_SA2[bb*Dm + c+2], v.z*v.z);
        atomicAdd(&d_SA1[bb*Dm + c+3], v.w); atomicAdd(&d_SA2[bb*Dm + c+3], v.w*v.w);
    }
}

// --------- W1 GEMM: A = instancenorm(Y) on the fly; T1 = relu(A@W1^T + b1) ----
// 64x64 tiles, K=Dm.
__global__ void k_gemmW1(const float* __restrict__ Bm, const float* __restrict__ bias,
                         const float* __restrict__ n1w, const float* __restrict__ n1b,
                         float* __restrict__ C)
{
    __shared__ __align__(16) float As[2][16][68];
    __shared__ __align__(16) float Bs[2][16][68];
    const int M = Bsz*N1;
    int tid = threadIdx.x;
    int tr = tid >> 4, tc = tid & 15;
    int r0 = blockIdx.y*64, c0 = blockIdx.x*64;
    int lr = tid >> 2;
    int lc = (tid & 3) * 4;
    int gr = r0 + lr, gc = c0 + lr;
    const float4 z4 = make_float4(0.f,0.f,0.f,0.f);
    int abb = (gr >= N1) ? 1 : 0;
    auto fetchA = [&](int s) -> float4 {
        if (gr >= M) return z4;
        int d = s*16 + lc;
        float4 x  = *(const float4*)(d_Y + (size_t)gr*Dm + d);
        float4 s1 = *(const float4*)(d_SA1 + abb*Dm + d);
        float4 s2 = *(const float4*)(d_SA2 + abb*Dm + d);
        float4 w4 = *(const float4*)(n1w + d);
        float4 b4 = *(const float4*)(n1b + d);
        float mux = s1.x*(1.f/N1), muy = s1.y*(1.f/N1), muz = s1.z*(1.f/N1), muw = s1.w*(1.f/N1);
        float scx = rsqrtf(s2.x*(1.f/N1) - mux*mux + EPSf)*w4.x;
        float scy = rsqrtf(s2.y*(1.f/N1) - muy*muy + EPSf)*w4.y;
        float scz = rsqrtf(s2.z*(1.f/N1) - muz*muz + EPSf)*w4.z;
        float scw = rsqrtf(s2.w*(1.f/N1) - muw*muw + EPSf)*w4.w;
        return make_float4((x.x-mux)*scx + b4.x, (x.y-muy)*scy + b4.y,
                           (x.z-muz)*scz + b4.z, (x.w-muw)*scw + b4.w);
    };
    float4 va = fetchA(0);
    float4 vb = *(const float4*)(Bm + (size_t)gc*Dm + lc);
    As[0][lc+0][lr]=va.x; As[0][lc+1][lr]=va.y; As[0][lc+2][lr]=va.z; As[0][lc+3][lr]=va.w;
    Bs[0][lc+0][lr]=vb.x; Bs[0][lc+1][lr]=vb.y; Bs[0][lc+2][lr]=vb.z; Bs[0][lc+3][lr]=vb.w;
    __syncthreads();
    float acc[4][4] = {};
    #pragma unroll
    for (int s = 0; s < 8; s++) {
        int cur = s & 1;
        if (s < 7) {
            va = fetchA(s+1);
            vb = *(const float4*)(Bm + (size_t)gc*Dm + (s+1)*16 + lc);
        }
        #pragma unroll
        for (int k = 0; k < 16; k++) {
            float4 a4 = *(const float4*)&As[cur][k][tr*4];
            float4 b4 = *(const float4*)&Bs[cur][k][tc*4];
            float a[4] = {a4.x, a4.y, a4.z, a4.w};
            float bv[4] = {b4.x, b4.y, b4.z, b4.w};
            #pragma unroll
            for (int i = 0; i < 4; i++)
                #pragma unroll
                for (int j = 0; j < 4; j++) acc[i][j] += a[i]*bv[j];
        }
        if (s < 7) {
            int nxt = cur ^ 1;
            As[nxt][lc+0][lr]=va.x; As[nxt][lc+1][lr]=va.y; As[nxt][lc+2][lr]=va.z; As[nxt][lc+3][lr]=va.w;
            Bs[nxt][lc+0][lr]=vb.x; Bs[nxt][lc+1][lr]=vb.y; Bs[nxt][lc+2][lr]=vb.z; Bs[nxt][lc+3][lr]=vb.w;
            __syncthreads();
        }
    }
    int c = c0 + tc*4;
    float4 bz = *(const float4*)(bias + c);
    #pragma unroll
    for (int i = 0; i < 4; i++) {
        int r = r0 + tr*4 + i;
        if (r >= M) continue;
        float4 v = make_float4(fmaxf(acc[i][0]+bz.x, 0.f), fmaxf(acc[i][1]+bz.y, 0.f),
                               fmaxf(acc[i][2]+bz.z, 0.f), fmaxf(acc[i][3]+bz.w, 0.f));
        *(float4*)(C + (size_t)r*Dff + c) = v;
    }
}

// --------- W2 GEMM: T2 = T1@W2^T + b2 + instancenorm(Y); T2 col-stats -> SB ---
// 32x64 tiles, K=Dff.
__global__ void k_gemmW2(const float* __restrict__ Bm, const float* __restrict__ bias,
                         const float* __restrict__ n1w, const float* __restrict__ n1b,
                         float* __restrict__ C)
{
    __shared__ __align__(16) float As[2][16][36];
    __shared__ __align__(16) float Bs[2][16][68];
    const int M = Bsz*N1;
    int tid = threadIdx.x;
    int tr = tid >> 4, tc = tid & 15;
    int r0 = blockIdx.y*32, c0 = blockIdx.x*64;
    int lr = tid >> 2;
    int lc = (tid & 3) * 4;
    bool aload = tid < 128;
    int ar = tid >> 2;
    int gr = r0 + ar, gc = c0 + lr;
    const float4 z4 = make_float4(0.f,0.f,0.f,0.f);
    float4 va = (aload && gr < M) ? *(const float4*)(d_T1 + (size_t)gr*Dff + lc) : z4;
    float4 vb = *(const float4*)(Bm + (size_t)gc*Dff + lc);
    if (aload) {
        As[0][lc+0][ar]=va.x; As[0][lc+1][ar]=va.y; As[0][lc+2][ar]=va.z; As[0][lc+3][ar]=va.w;
    }
    Bs[0][lc+0][lr]=vb.x; Bs[0][lc+1][lr]=vb.y; Bs[0][lc+2][lr]=vb.z; Bs[0][lc+3][lr]=vb.w;
    __syncthreads();
    float acc[2][4] = {};
    const int S = Dff >> 4;
    for (int s = 0; s < S; s++) {
        int cur = s & 1;
        if (s + 1 < S) {
            va = (aload && gr < M) ? *(const float4*)(d_T1 + (size_t)gr*Dff + (s+1)*16 + lc) : z4;
            vb = *(const float4*)(Bm + (size_t)gc*Dff + (s+1)*16 + lc);
        }
        #pragma unroll
        for (int k = 0; k < 16; k++) {
            float2 a2 = *(const float2*)&As[cur][k][tr*2];
            float4 b4 = *(const float4*)&Bs[cur][k][tc*4];
            acc[0][0] += a2.x*b4.x; acc[0][1] += a2.x*b4.y;
            acc[0][2] += a2.x*b4.z; acc[0][3] += a2.x*b4.w;
            acc[1][0] += a2.y*b4.x; acc[1][1] += a2.y*b4.y;
            acc[1][2] += a2.y*b4.z; acc[1][3] += a2.y*b4.w;
        }
        if (s + 1 < S) {
            int nxt = cur ^ 1;
            if (aload) {
                As[nxt][lc+0][ar]=va.x; As[nxt][lc+1][ar]=va.y; As[nxt][lc+2][ar]=va.z; As[nxt][lc+3][ar]=va.w;
            }
            Bs[nxt][lc+0][lr]=vb.x; Bs[nxt][lc+1][lr]=vb.y; Bs[nxt][lc+2][lr]=vb.z; Bs[nxt][lc+3][lr]=vb.w;
            __syncthreads();
        }
    }
    int c = c0 + tc*4;
    float4 bz = *(const float4*)(bias + c);
    #pragma unroll
    for (int i = 0; i < 2; i++) {
        int r = r0 + tr*2 + i;
        if (r >= M) continue;
        int bb = (r >= N1) ? 1 : 0;
        // residual = instancenorm(Y[r][c..]) with SA stats
        float4 x  = *(const float4*)(d_Y + (size_t)r*Dm + c);
        float4 s1 = *(const float4*)(d_SA1 + bb*Dm + c);
        float4 s2 = *(const float4*)(d_SA2 + bb*Dm + c);
        float4 w4 = *(const float4*)(n1w + c);
        float4 b4 = *(const float4*)(n1b + c);
        float mux = s1.x*(1.f/N1), muy = s1.y*(1.f/N1), muz = s1.z*(1.f/N1), muw = s1.w*(1.f/N1);
        float scx = rsqrtf(s2.x*(1.f/N1) - mux*mux + EPSf)*w4.x;
        float scy = rsqrtf(s2.y*(1.f/N1) - muy*muy + EPSf)*w4.y;
        float scz = rsqrtf(s2.z*(1.f/N1) - muz*muz + EPSf)*w4.z;
        float scw = rsqrtf(s2.w*(1.f/N1) - muw*muw + EPSf)*w4.w;
        float4 v = make_float4(acc[i][0]+bz.x + (x.x-mux)*scx + b4.x,
                               acc[i][1]+bz.y + (x.y-muy)*scy + b4.y,
                               acc[i][2]+bz.z + (x.z-muz)*scz + b4.z,
                               acc[i][3]+bz.w + (x.w-muw)*scw + b4.w);
        *(float4*)(C + (size_t)r*Dm + c) = v;
        atomicAdd(&d_SB1[bb*Dm + c+0], v.x); atomicAdd(&d_SB2[bb*Dm + c+0], v.x*v.x);
        atomicAdd(&d_SB1[bb*Dm + c+1], v.y); atomicAdd(&d_SB2[bb*Dm + c+1], v.y*v.y);
        atomicAdd(&d_SB1[bb*Dm + c+2], v.z); atomicAdd(&d_SB2[bb*Dm + c+2], v.z*v.z);
        atomicAdd(&d_SB1[bb*Dm + c+3], v.w); atomicAdd(&d_SB2[bb*Dm + c+3], v.w*v.w);
    }
}

// ------------------------- sparse attention, split-K + fused dense -----------
__device__ __forceinline__ void attn_word20(unsigned word, int base,
    const float4 q4[4], float cqx, float cqy,
    const float (*Ks)[20], const float (*Vs)[20],
    const float* ckx, const float* cky, const float* qerow,
    float& lrun, float acc[16])
{
    while (word) {
        int mm = base + (__ffs((int)word) - 1);
        word &= word - 1u;
        const float4* kp = (const float4*)Ks[mm];
        float4 k0 = kp[0], k1 = kp[1], k2 = kp[2], k3 = kp[3];
        float s = q4[0].x*k0.x + q4[0].y*k0.y + q4[0].z*k0.z + q4[0].w*k0.w
                + q4[1].x*k1.x + q4[1].y*k1.y + q4[1].z*k1.z + q4[1].w*k1.w
                + q4[2].x*k2.x + q4[2].y*k2.y + q4[2].z*k2.z + q4[2].w*k2.w
                + q4[3].x*k3.x + q4[3].y*k3.y + q4[3].z*k3.z + q4[3].w*k3.w;
        float dx = cqx - ckx[mm], dy = cqy - cky[mm];
        float dist = sqrtf(dx*dx + dy*dy);
        int bk = (int)(dist * 32.f); if (bk > 31) bk = 31;
        float p = __expf(s*SCALEf + qerow[bk]);
        lrun += p;
        const float4* vp = (const float4*)Vs[mm];
        float4 v0 = vp[0], v1 = vp[1], v2 = vp[2], v3 = vp[3];
        acc[ 0] += p*v0.x; acc[ 1] += p*v0.y; acc[ 2] += p*v0.z; acc[ 3] += p*v0.w;
        acc[ 4] += p*v1.x; acc[ 5] += p*v1.y; acc[ 6] += p*v1.z; acc[ 7] += p*v1.w;
        acc[ 8] += p*v2.x; acc[ 9] += p*v2.y; acc[10] += p*v2.z; acc[11] += p*v2.w;
        acc[12] += p*v3.x; acc[13] += p*v3.y; acc[14] += p*v3.z; acc[15] += p*v3.w;
    }
}

// grid (25, Hh, Bsz), 128 threads. x<24: sparse (qtile=x/3, kseg=x%3).
// x==24: dense rows {0, Nn} (64 threads each).
__global__ void k_attn(const float* __restrict__ coords)
{
    __shared__ float Ks[128][20];
    __shared__ float Vs[128][20];
    __shared__ float ckx[128], cky[128];
    __shared__ float qes[128][33];
    __shared__ float pw[4][17];
    int b = blockIdx.z, h = blockIdx.y;
    int x = blockIdx.x;
    int tid = threadIdx.x;
    const size_t hb = (size_t)(b*Hh + h)*N1;

    if (x == 24) {   // ---- dense rows ----
        int sub = tid >> 6, st = tid & 63;
        int lane = tid & 31, w = tid >> 5;
        int n = sub ? Nn : 0;
        float q[16];
        const float4* qp = (const float4*)(d_Q + (hb + n)*Dk);
        #pragma unroll
        for (int i = 0; i < 4; i++) {
            float4 v = qp[i];
            q[i*4+0]=v.x; q[i*4+1]=v.y; q[i*4+2]=v.z; q[i*4+3]=v.w;
        }
        float cqx = 0.f, cqy = 0.f;
        if (n < Nn) { cqx = coords[(b*Nn+n)*2]; cqy = coords[(b*Nn+n)*2+1]; }
        const float* qerow = d_QE + (hb + n)*NBk;
        float l = 0.f, acc[16];
        #pragma unroll
        for (int d = 0; d < 16; d++) acc[d] = 0.f;
        const float* Kt = d_Kb + hb*Dk;
        const float* Vt = d_Vb + hb*Dk;
        for (int mk = st; mk < N1; mk += 64) {
            const float4* kp = (const float4*)(Kt + (size_t)mk*Dk);
            float s = 0.f;
            #pragma unroll
            for (int i = 0; i < 4; i++) {
                float4 kv = kp[i];
                s += q[i*4+0]*kv.x + q[i*4+1]*kv.y + q[i*4+2]*kv.z + q[i*4+3]*kv.w;
            }
            float cmx = 0.f, cmy = 0.f;
            if (mk < Nn) { cmx = coords[(b*Nn+mk)*2]; cmy = coords[(b*Nn+mk)*2+1]; }
            float dx = cqx - cmx, dy = cqy - cmy;
            float dist = sqrtf(dx*dx + dy*dy);
            int bk = (int)(dist * 32.f); if (bk > 31) bk = 31;
            float p = __expf(s*SCALEf + qerow[bk]);
            l += p;
            const float4* vp = (const float4*)(Vt + (size_t)mk*Dk);
            #pragma unroll
            for (int i = 0; i < 4; i++) {
                float4 vv = vp[i];
                acc[i*4+0] += p*vv.x; acc[i*4+1] += p*vv.y;
                acc[i*4+2] += p*vv.z; acc[i*4+3] += p*vv.w;
            }
        }
        #pragma unroll
        for (int o = 16; o; o >>= 1) {
            l += __shfl_xor_sync(0xffffffffu, l, o);
            #pragma unroll
            for (int d = 0; d < 16; d++) acc[d] += __shfl_xor_sync(0xffffffffu, acc[d], o);
        }
        if (lane == 0) {
            #pragma unroll
            for (int d = 0; d < 16; d++) pw[w][d] = acc[d];
            pw[w][16] = l;
        }
        __syncthreads();
        if (tid == 0 || tid == 64) {
            int w0 = sub*2;
            float L = pw[w0][16] + pw[w0+1][16];
            float inv = 1.f / L;
            float* o = d_CTX + ((size_t)(b*N1 + n))*Dm + h*Dk;
            #pragma unroll
            for (int d = 0; d < 16; d++) o[d] = (pw[w0][d] + pw[w0+1][d]) * inv;
        }
        return;
    }

    // ---- sparse split-K ----
    int qt = x / 3, kseg = x % 3;
    int n = qt*128 + tid;              // 0..1023
    bool qv = (n != 0);                // row 0 is dense
    float4 q4[4];
    float cqx = 0.f, cqy = 0.f, lrun = 0.f;
    float acc[16];
    #pragma unroll
    for (int d = 0; d < 16; d++) acc[d] = 0.f;
    const unsigned* rowadj = d_ADJ + (size_t)(b*N1 + n)*AW;
    {
        const float4* qp = (const float4*)(d_Q + (hb + n)*Dk);
        #pragma unroll
        for (int i = 0; i < 4; i++) q4[i] = qp[i];
        cqx = coords[(b*Nn+n)*2]; cqy = coords[(b*Nn+n)*2+1];
        const float4* qep = (const float4*)(d_QE + (hb + n)*NBk);
        #pragma unroll
        for (int i = 0; i < 8; i++) {
            float4 v = qep[i];
            qes[tid][i*4+0]=v.x; qes[tid][i*4+1]=v.y;
            qes[tid][i*4+2]=v.z; qes[tid][i*4+3]=v.w;
        }
    }
    for (int kt = kseg*3; kt < kseg*3 + 3; kt++) {
        int m0 = kt*128;
        int tlen = N1 - m0; if (tlen > 128) tlen = 128;
        const float4* Kt = (const float4*)(d_Kb + (hb + m0)*Dk);
        const float4* Vt = (const float4*)(d_Vb + (hb + m0)*Dk);
        __syncthreads();
        #pragma unroll
        for (int i = 0; i < 4; i++) {
            int f = tid + i*128;
            int row = f >> 2, j = (f & 3)*4;
            if (row < tlen) {
                *(float4*)&Ks[row][j] = Kt[f];
                *(float4*)&Vs[row][j] = Vt[f];
            }
        }
        if (tid < tlen) {
            int m = m0 + tid;
            if (m < Nn) { ckx[tid] = coords[(b*Nn+m)*2]; cky[tid] = coords[(b*Nn+m)*2+1]; }
            else        { ckx[tid] = 0.f; cky[tid] = 0.f; }
        }
        __syncthreads();
        if (!qv) continue;
        int wb = m0 >> 5;
        unsigned w0 = rowadj[wb];
        unsigned w1 = (wb+1 < AW) ? rowadj[wb+1] : 0u;
        unsigned w2 = (wb+2 < AW) ? rowadj[wb+2] : 0u;
        unsigned w3 = (wb+3 < AW) ? rowadj[wb+3] : 0u;
        attn_word20(w0,  0, q4, cqx, cqy, Ks, Vs, ckx, cky, qes[tid], lrun, acc);
        attn_word20(w1, 32, q4, cqx, cqy, Ks, Vs, ckx, cky, qes[tid], lrun, acc);
        attn_word20(w2, 64, q4, cqx, cqy, Ks, Vs, ckx, cky, qes[tid], lrun, acc);
        attn_word20(w3, 96, q4, cqx, cqy, Ks, Vs, ckx, cky, qes[tid], lrun, acc);
    }
    if (qv) {
        size_t base = ((size_t)kseg*Bsz*N1 + (size_t)b*N1 + n)*Hh + h;
        float* pa = d_PA + base*PASTR;
        *(float4*)(pa+ 0) = make_float4(acc[ 0], acc[ 1], acc[ 2], acc[ 3]);
        *(float4*)(pa+ 4) = make_float4(acc[ 4], acc[ 5], acc[ 6], acc[ 7]);
        *(float4*)(pa+ 8) = make_float4(acc[ 8], acc[ 9], acc[10], acc[11]);
        *(float4*)(pa+12) = make_float4(acc[12], acc[13], acc[14], acc[15]);
        pa[16] = lrun;
    }
}

// ------------------------- instance norm apply: T2 -> HG (via SB totals) -----
// grid (Bsz, 4, 8), 1024 threads. Also g += mean(out_h), POOL += mean(out_h).
__global__ void k_iapply(const float* __restrict__ src, float* __restrict__ dst,
                         const float* __restrict__ w, const float* __restrict__ bb)
{
    int b  = blockIdx.x;
    int dl = threadIdx.x & 31;
    int g  = threadIdx.x >> 5;
    int d  = blockIdx.y*32 + dl;
    int z  = blockIdx.z;
    float S1 = d_SB1[b*Dm + d];
    float S2 = d_SB2[b*Dm + d];
    float mu  = S1 * (1.f/N1);
    float var = S2 * (1.f/N1) - mu*mu;
    float sc  = rsqrtf(var + EPSf) * w[d];
    float sh  = bb[d];
    const float* p = src + (size_t)b*N1*Dm + d;
    float* o = dst + (size_t)b*N1*Dm + d;
    float mo = ((S1 - p[(size_t)Nn*Dm])*(1.f/Nn) - mu)*sc + sh;
    int n0 = z*128, n1 = (z == 7) ? N1 : (z+1)*128;
    for (int n = n0 + g; n < n1; n += 32) {
        float val = (p[(size_t)n*Dm] - mu)*sc + sh;
        if (n == Nn) val += mo;
        o[(size_t)n*Dm] = val;
    }
    if (z == 7 && g == 0) d_POOL[b*Dm + d] += mo;
}

// ------------------------- final GEMM: out = (h + pool/3) @ outW^T + outb ----
__global__ void k_fgemm(const float* __restrict__ Bm, const float* __restrict__ bias,
                        float* __restrict__ out)
{
    __shared__ __align__(16) float As[2][16][68];
    __shared__ __align__(16) float Bs[2][16][68];
    int tid = threadIdx.x;
    int tr = tid >> 4, tc = tid & 15;
    int r0 = blockIdx.y*64, c0 = blockIdx.x*64;
    int lr = tid >> 2;
    int lc = (tid & 3) * 4;
    int gr = r0 + lr;
    int bb = gr >> 10, nn = gr & 1023;
    const float* Arow = d_HG + ((size_t)bb*N1 + nn)*Dm;
    const float* Prow = d_POOL + bb*Dm;
    int gc = c0 + lr;
    if (blockIdx.x == 0 && blockIdx.y == 0 && tid < Bsz*Dm)
        out[Bsz*Nn*Dm + tid] = d_POOL[tid] * (1.f/3.f);
    float4 va, vb;
    {
        float4 hv = *(const float4*)(Arow + lc);
        float4 pv = *(const float4*)(Prow + lc);
        va = make_float4(hv.x + pv.x*(1.f/3.f), hv.y + pv.y*(1.f/3.f),
                         hv.z + pv.z*(1.f/3.f), hv.w + pv.w*(1.f/3.f));
        vb = *(const float4*)(Bm + (size_t)gc*Dm + lc);
    }
    As[0][lc+0][lr]=va.x; As[0][lc+1][lr]=va.y; As[0][lc+2][lr]=va.z; As[0][lc+3][lr]=va.w;
    Bs[0][lc+0][lr]=vb.x; Bs[0][lc+1][lr]=vb.y; Bs[0][lc+2][lr]=vb.z; Bs[0][lc+3][lr]=vb.w;
    __syncthreads();
    float acc[4][4] = {};
    #pragma unroll
    for (int s = 0; s < 8; s++) {
        int cur = s & 1;
        if (s < 7) {
            float4 hv = *(const float4*)(Arow + (s+1)*16 + lc);
            float4 pv = *(const float4*)(Prow + (s+1)*16 + lc);
            va = make_float4(hv.x + pv.x*(1.f/3.f), hv.y + pv.y*(1.f/3.f),
                             hv.z + pv.z*(1.f/3.f), hv.w + pv.w*(1.f/3.f));
            vb = *(const float4*)(Bm + (size_t)gc*Dm + (s+1)*16 + lc);
        }
        #pragma unroll
        for (int k = 0; k < 16; k++) {
            float4 a4 = *(const float4*)&As[cur][k][tr*4];
            float4 b4 = *(const float4*)&Bs[cur][k][tc*4];
            float a[4] = {a4.x, a4.y, a4.z, a4.w};
            float bv[4] = {b4.x, b4.y, b4.z, b4.w};
            #pragma unroll
            for (int i = 0; i < 4; i++)
                #pragma unroll
                for (int j = 0; j < 4; j++) acc[i][j] += a[i]*bv[j];
        }
        if (s < 7) {
            int nxt = cur ^ 1;
            As[nxt][lc+0][lr]=va.x; As[nxt][lc+1][lr]=va.y; As[nxt][lc+2][lr]=va.z; As[nxt][lc+3][lr]=va.w;
            Bs[nxt][lc+0][lr]=vb.x; Bs[nxt][lc+1][lr]=vb.y; Bs[nxt][lc+2][lr]=vb.z; Bs[nxt][lc+3][lr]=vb.w;
            __syncthreads();
        }
    }
    int c = c0 + tc*4;
    float4 bz = *(const float4*)(bias + c);
    #pragma unroll
    for (int i = 0; i < 4; i++) {
        int r = r0 + tr*4 + i;
        *(float4*)(out + (size_t)r*Dm + c) =
            make_float4(acc[i][0]+bz.x, acc[i][1]+bz.y, acc[i][2]+bz.z, acc[i][3]+bz.w);
    }
}

// ------------------------- host driver ---------------------------------------
extern "C" void kernel_launch(void* const* d_in, const int* in_sizes, int n_in,
                              void* d_out, int out_size)
{
    const float* coords = (const float*)d_in[0];
    const float* in_W   = (const float*)d_in[1];
    const float* in_b   = (const float*)d_in[2];
    const float* gnode  = (const float*)d_in[3];
    const float* Wq     = (const float*)d_in[4];
    const float* Wk     = (const float*)d_in[5];
    const float* Wv     = (const float*)d_in[6];
    const float* Wo     = (const float*)d_in[7];
    const float* emb    = (const float*)d_in[8];
    const float* W1     = (const float*)d_in[9];
    const float* b1     = (const float*)d_in[10];
    const float* W2     = (const float*)d_in[11];
    const float* b2     = (const float*)d_in[12];
    const float* n1w    = (const float*)d_in[13];
    const float* n1b    = (const float*)d_in[14];
    const float* n2w    = (const float*)d_in[15];
    const float* n2b    = (const float*)d_in[16];
    const float* outW   = (const float*)d_in[17];
    const float* outb   = (const float*)d_in[18];
    float* out = (float*)d_out;

    float *HG, *Y, *T1, *T2;
    cudaGetSymbolAddress((void**)&HG,  d_HG);
    cudaGetSymbolAddress((void**)&Y,   d_Y);
    cudaGetSymbolAddress((void**)&T1,  d_T1);
    cudaGetSymbolAddress((void**)&T2,  d_T2);

    const int Mall = Bsz*N1;  // 2050

    k_input<<<(Bsz*N1*Dm + 255)/256, 256>>>(coords, in_W, in_b, gnode);
    k_colmean<<<Bsz, 1024>>>();                            // layer-0 g update

    for (int l = 0; l < 3; l++) {
        k_par1<<<983, 256>>>(Wq + (size_t)l*Dm*Dm, Wk + (size_t)l*Dm*Dm, Wv + (size_t)l*Dm*Dm);
        k_par2<<<769, 256>>>(emb + (size_t)l*NBk*Dm);
        { dim3 ga(25, Hh, Bsz); k_attn<<<ga, 128>>>(coords); }

        { dim3 gq(Dm/64, (Mall + 31)/32);
          k_gemmC<<<gq, 256>>>(Wo + (size_t)l*Dm*Dm, Y); }
        { dim3 g1(Dff/64, (Mall + 63)/64);
          k_gemmW1<<<g1, 256>>>(W1 + (size_t)l*Dff*Dm, b1 + l*Dff, n1w + l*Dm, n1b + l*Dm, T1); }
        { dim3 g2(Dm/64, (Mall + 31)/32);
          k_gemmW2<<<g2, 256>>>(W2 + (size_t)l*Dm*Dff, b2 + l*Dm, n1w + l*Dm, n1b + l*Dm, T2); }
        { dim3 gi(Bsz, 4, 8); k_iapply<<<gi, 1024>>>(T2, HG, n2w + l*Dm, n2b + l*Dm); }
    }

    { dim3 ge(Dm/64, (Bsz*Nn)/64); k_fgemm<<<ge, 256>>>(outW, outb, out); }
}

// round 13
// speedup vs baseline: 1.5743x; 1.5743x over previous
#include <cuda_runtime.h>
#include <math_constants.h>
#include <math.h>

#define Bsz 2
#define Nn 1024
#define N1 1025
#define Dm 128
#define Hh 8
#define Dk 16
#define Dff 512
#define NBk 32
#define KNN 10
#define AW 33          // 33 x 32-bit words cover 1025 mask bits per row
#define EPSf 1e-5f
#define SCALEf 0.25f   // 1/sqrt(16)
#define NCH 17         // inorm stat chunks
#define PASTR 20       // split-K partial stride (floats), 16B-aligned

// ------------------------- persistent device scratch -------------------------
__device__ float    d_HG [Bsz*N1*Dm];     // state: rows 0..1023 = h, row 1024 = g
__device__ float    d_POOL[Bsz*Dm];
__device__ float    d_D2 [(size_t)Bsz*Nn*Nn];
__device__ unsigned d_ADJ[Bsz*N1*AW];
__device__ float    d_Q  [Bsz*Hh*N1*Dk];  // head-major: [b][h][n][dk]
__device__ float    d_Kb [Bsz*Hh*N1*Dk];
__device__ float    d_Vb [Bsz*Hh*N1*Dk];
__device__ float    d_CTX[Bsz*N1*Dm];
__device__ float    d_QE [Bsz*Hh*N1*NBk]; // head-major: [b][h][n][bucket]
__device__ float    d_Y  [Bsz*N1*Dm];
__device__ float    d_T1 [Bsz*N1*Dff];
__device__ float    d_T2 [Bsz*N1*Dm];
__device__ float    d_PS1[Bsz*NCH*Dm];
__device__ float    d_PS2[Bsz*NCH*Dm];
__device__ float    d_PA [3*Bsz*N1*Hh*PASTR];  // split-K partials: acc[16]+lrun

// ------------------------- input embedding + state init ----------------------
__global__ void k_input(const float* __restrict__ coords, const float* __restrict__ inW,
                        const float* __restrict__ inb, const float* __restrict__ gnode)
{
    int gid = blockIdx.x*blockDim.x + threadIdx.x;
    if (gid < Bsz*Dm) d_POOL[gid] = 0.f;
    if (gid >= Bsz*N1*Dm) return;
    int d = gid % Dm;
    int n = (gid / Dm) % N1;
    int b = gid / (Dm*N1);
    float v;
    if (n < Nn) {
        float x = coords[(b*Nn+n)*2+0];
        float y = coords[(b*Nn+n)*2+1];
        v = x*inW[d*2+0] + y*inW[d*2+1] + inb[d];
    } else {
        v = gnode[d];
    }
    d_HG[gid] = v;
}

// ------------------------- layer-0 g update: g += mean(h) --------------------
__global__ void k_colmean()
{
    __shared__ float red[8][Dm];
    int b = blockIdx.x;
    int d = threadIdx.x & 127;
    int g = threadIdx.x >> 7;
    const float* base = d_HG + (size_t)b*N1*Dm;
    float s = 0.f;
    for (int n = g; n < Nn; n += 8) s += base[n*Dm + d];
    red[g][d] = s;
    __syncthreads();
    if (g == 0) {
        float t = 0.f;
        #pragma unroll
        for (int i = 0; i < 8; i++) t += red[i][d];
        d_HG[(size_t)b*N1*Dm + Nn*Dm + d] += t * (1.f/Nn);
    }
}

// ===================== PAR1: D2 (self-norms) + QKV + ADJ-init =================
// grid: [0,272) d2 tiles, [272,470) qkv, [470,983) adjacency rows. 256 threads.
__global__ void k_par1(const float* __restrict__ wq, const float* __restrict__ wk,
                       const float* __restrict__ wv)
{
    __shared__ __align__(16) float As[2][16][68];
    __shared__ __align__(16) float Bs[2][16][68];
    __shared__ float rsq[64], csq[64];
    int bx = blockIdx.x;
    int tid = threadIdx.x;

    if (bx < 272) {        // ---------- D2 symmetric tile ----------
        int b = bx / 136;
        int x = bx % 136, bi = 0;
        while (x >= 16 - bi) { x -= 16 - bi; bi++; }
        int bj = bi + x;
        const float* A = d_HG + (size_t)b*N1*Dm;
        int tr = tid >> 4, tc = tid & 15;
        int r0 = bi*64, c0 = bj*64;
        int lr = tid >> 2, lc = (tid & 3)*4;
        float rn = 0.f, cn = 0.f;
        float4 va = *(const float4*)(A + (size_t)(r0+lr)*Dm + lc);
        float4 vb = *(const float4*)(A + (size_t)(c0+lr)*Dm + lc);
        rn += va.x*va.x + va.y*va.y + va.z*va.z + va.w*va.w;
        cn += vb.x*vb.x + vb.y*vb.y + vb.z*vb.z + vb.w*vb.w;
        As[0][lc+0][lr]=va.x; As[0][lc+1][lr]=va.y; As[0][lc+2][lr]=va.z; As[0][lc+3][lr]=va.w;
        Bs[0][lc+0][lr]=vb.x; Bs[0][lc+1][lr]=vb.y; Bs[0][lc+2][lr]=vb.z; Bs[0][lc+3][lr]=vb.w;
        __syncthreads();
        float acc[4][4] = {};
        #pragma unroll
        for (int s = 0; s < 8; s++) {
            int cur = s & 1;
            if (s < 7) {
                va = *(const float4*)(A + (size_t)(r0+lr)*Dm + (s+1)*16 + lc);
                vb = *(const float4*)(A + (size_t)(c0+lr)*Dm + (s+1)*16 + lc);
                rn += va.x*va.x + va.y*va.y + va.z*va.z + va.w*va.w;
                cn += vb.x*vb.x + vb.y*vb.y + vb.z*vb.z + vb.w*vb.w;
            }
            #pragma unroll
            for (int k = 0; k < 16; k++) {
                float4 a4 = *(const float4*)&As[cur][k][tr*4];
                float4 b4 = *(const float4*)&Bs[cur][k][tc*4];
                float a[4] = {a4.x, a4.y, a4.z, a4.w};
                float bv[4] = {b4.x, b4.y, b4.z, b4.w};
                #pragma unroll
                for (int i = 0; i < 4; i++)
                    #pragma unroll
                    for (int j = 0; j < 4; j++) acc[i][j] += a[i]*bv[j];
            }
            if (s < 7) {
                int nxt = cur ^ 1;
                As[nxt][lc+0][lr]=va.x; As[nxt][lc+1][lr]=va.y; As[nxt][lc+2][lr]=va.z; As[nxt][lc+3][lr]=va.w;
                Bs[nxt][lc+0][lr]=vb.x; Bs[nxt][lc+1][lr]=vb.y; Bs[nxt][lc+2][lr]=vb.z; Bs[nxt][lc+3][lr]=vb.w;
                __syncthreads();
            }
        }
        rn += __shfl_xor_sync(0xffffffffu, rn, 1);
        rn += __shfl_xor_sync(0xffffffffu, rn, 2);
        cn += __shfl_xor_sync(0xffffffffu, cn, 1);
        cn += __shfl_xor_sync(0xffffffffu, cn, 2);
        if ((tid & 3) == 0) { rsq[lr] = rn; csq[lr] = cn; }
        __syncthreads();
        float vals[4][4];
        #pragma unroll
        for (int i = 0; i < 4; i++) {
            int r = r0 + tr*4 + i;
            float sqr = rsq[tr*4 + i];
            float* orow = d_D2 + ((size_t)b*Nn + r)*Nn + c0 + tc*4;
            float o[4];
            #pragma unroll
            for (int j = 0; j < 4; j++) {
                int c = c0 + tc*4 + j;
                float v = sqr + csq[tc*4 + j] - 2.f*acc[i][j];
                o[j] = (r == c) ? CUDART_INF_F : v;
                vals[i][j] = o[j];
            }
            *(float4*)orow = make_float4(o[0], o[1], o[2], o[3]);
        }
        if (bi != bj) {
            #pragma unroll
            for (int j = 0; j < 4; j++) {
                int c = c0 + tc*4 + j;
                float* orow = d_D2 + ((size_t)b*Nn + c)*Nn + r0 + tr*4;
                *(float4*)orow = make_float4(vals[0][j], vals[1][j], vals[2][j], vals[3][j]);
            }
        }
        return;
    }

    if (bx < 470) {        // ---------- QKV GEMM ----------
        int idx = bx - 272;
        int sel = idx / 66, rem = idx % 66;
        const float* Bm = (sel == 0) ? wq : (sel == 1) ? wk : wv;
        float* C = (sel == 0) ? d_Q : (sel == 1) ? d_Kb : d_Vb;
        const int M = Bsz*N1;
        int tr = tid >> 4, tc = tid & 15;
        int r0 = (rem >> 1)*64, c0 = (rem & 1)*64;
        int lr = tid >> 2, lc = (tid & 3)*4;
        int gr = r0 + lr, gc = c0 + lr;
        const float4 z4 = make_float4(0.f,0.f,0.f,0.f);
        float4 va = (gr < M) ? *(const float4*)(d_HG + (size_t)gr*Dm + lc) : z4;
        float4 vb = *(const float4*)(Bm + (size_t)gc*Dm + lc);
        As[0][lc+0][lr]=va.x; As[0][lc+1][lr]=va.y; As[0][lc+2][lr]=va.z; As[0][lc+3][lr]=va.w;
        Bs[0][lc+0][lr]=vb.x; Bs[0][lc+1][lr]=vb.y; Bs[0][lc+2][lr]=vb.z; Bs[0][lc+3][lr]=vb.w;
        __syncthreads();
        float acc[4][4] = {};
        #pragma unroll
        for (int s = 0; s < 8; s++) {
            int cur = s & 1;
            if (s < 7) {
                va = (gr < M) ? *(const float4*)(d_HG + (size_t)gr*Dm + (s+1)*16 + lc) : z4;
                vb = *(const float4*)(Bm + (size_t)gc*Dm + (s+1)*16 + lc);
            }
            #pragma unroll
            for (int k = 0; k < 16; k++) {
                float4 a4 = *(const float4*)&As[cur][k][tr*4];
                float4 b4 = *(const float4*)&Bs[cur][k][tc*4];
                float a[4] = {a4.x, a4.y, a4.z, a4.w};
                float bv[4] = {b4.x, b4.y, b4.z, b4.w};
                #pragma unroll
                for (int i = 0; i < 4; i++)
                    #pragma unroll
                    for (int j = 0; j < 4; j++) acc[i][j] += a[i]*bv[j];
            }
            if (s < 7) {
                int nxt = cur ^ 1;
                As[nxt][lc+0][lr]=va.x; As[nxt][lc+1][lr]=va.y; As[nxt][lc+2][lr]=va.z; As[nxt][lc+3][lr]=va.w;
                Bs[nxt][lc+0][lr]=vb.x; Bs[nxt][lc+1][lr]=vb.y; Bs[nxt][lc+2][lr]=vb.z; Bs[nxt][lc+3][lr]=vb.w;
                __syncthreads();
            }
        }
        int c = c0 + tc*4;
        int h  = c >> 4;
        int dk = c & 15;
        #pragma unroll
        for (int i = 0; i < 4; i++) {
            int r = r0 + tr*4 + i;
            if (r >= M) continue;
            int bb = (r >= N1) ? 1 : 0;
            int n  = r - bb*N1;
            *(float4*)(C + ((size_t)(bb*Hh + h)*N1 + n)*Dk + dk) =
                make_float4(acc[i][0], acc[i][1], acc[i][2], acc[i][3]);
        }
        return;
    }

    // ---------- adjacency base pattern ----------
    {
        int row = (bx - 470)*4 + (tid >> 6);
        int t = tid & 63;
        if (row >= Bsz*N1 || t >= AW) return;
        int i = row % N1;
        int w = t;
        unsigned bits = 0u;
        #pragma unroll 4
        for (int q = 0; q < 32; q++) {
            int m = w*32 + q;
            if (m > Nn) break;
            bool on;
            if (i == Nn || m == Nn || i == m || i == 0 || m == 0) on = true;
            else {
                int di = i - m; if (di < 0) di = -di;
                on = ((i >> 7) == (m >> 7)) && (di <= 11);   // hier adjacency
            }
            if (on) bits |= 1u << q;
        }
        d_ADJ[row*AW + w] = bits;
    }
}

// ===================== PAR2: topk (2 warps/row) + qe (8 rows/block) ===========
// grid: [0,512) topk (4 rows x 2 warps), [512,769) qe (8 rows/block). 256 thr.
__global__ void k_par2(const float* __restrict__ emb)
{
    int bx = blockIdx.x;
    int tid = threadIdx.x;
    if (bx < 512) {        // ---------- exact top-10 kNN, 2 warps/row ----------
        __shared__ unsigned candK[2][4][2];
        __shared__ int      candJ[2][4][2];
        int wid  = tid >> 5;           // 0..7
        int lane = tid & 31;
        int rw   = wid >> 1;           // row within block 0..3
        int w    = wid & 1;            // column half 0/1
        int rowg = bx*4 + rw;          // 0..2047
        int b = rowg >> 10, i = rowg & 1023;
        const float* row = d_D2 + (size_t)rowg*Nn + w*512;
        unsigned uv[16];
        #pragma unroll
        for (int t = 0; t < 16; t++) {
            unsigned u = __float_as_uint(row[t*32 + lane]);
            uv[t] = (u & 0x80000000u) ? ~u : (u | 0x80000000u);
        }
        unsigned* adjb = d_ADJ + (size_t)b*N1*AW;
        for (int r = 0; r < KNN; r++) {
            unsigned m0 = min(uv[0], uv[4]),  m1 = min(uv[1], uv[5]);
            unsigned m2 = min(uv[2], uv[6]),  m3 = min(uv[3], uv[7]);
            m0 = min(m0, min(uv[8],  uv[12]));
            m1 = min(m1, min(uv[9],  uv[13]));
            m2 = min(m2, min(uv[10], uv[14]));
            m3 = min(m3, min(uv[11], uv[15]));
            unsigned mm = min(min(m0, m1), min(m2, m3));
            #pragma unroll
            for (int o = 16; o; o >>= 1)
                mm = min(mm, __shfl_xor_sync(0xffffffffu, mm, o));
            int lj = 0x7FFFFFFF;
            #pragma unroll
            for (int t = 0; t < 16; t++)
                if (uv[t] == mm) { lj = w*512 + t*32 + lane; break; }
            #pragma unroll
            for (int o = 16; o; o >>= 1)
                lj = min(lj, __shfl_xor_sync(0xffffffffu, lj, o));
            int pb = r & 1;
            if (lane == 0) { candK[pb][rw][w] = mm; candJ[pb][rw][w] = lj; }
            __syncthreads();
            unsigned k0 = candK[pb][rw][0], k1 = candK[pb][rw][1];
            int j0 = candJ[pb][rw][0], j1 = candJ[pb][rw][1];
            int bj;
            if (k0 < k1 || (k0 == k1 && j0 < j1)) bj = j0; else bj = j1;
            if (w == (bj >> 9)) {               // owning half clears the slot
                int jl = bj - w*512;
                if (lane == (jl & 31)) uv[jl >> 5] = 0xFFFFFFFFu;
            }
            if (w == 0 && lane == 0) {
                atomicOr(&adjb[i*AW + (bj >> 5)], 1u << (bj & 31));
                atomicOr(&adjb[bj*AW + (i >> 5)], 1u << (i & 31));
            }
        }
        return;
    }
    // ---------- qe: 8 rows per block ----------
    __shared__ float qs[8][Dm];
    int r0 = (bx - 512)*8;             // first global row (b*N1+n)
    if (tid < 128) {
        int hh = tid >> 4, dk = tid & 15;
        #pragma unroll
        for (int r = 0; r < 8; r++) {
            int row = r0 + r;
            if (row >= Bsz*N1) break;
            int b = (row >= N1) ? 1 : 0;
            int n = row - b*N1;
            qs[r][tid] = d_Q[((size_t)(b*Hh + hh)*N1 + n)*Dk + dk];
        }
    }
    __syncthreads();
    int h = tid >> 5, kb = tid & 31;
    float e[16];
    const float* ep = emb + kb*Dm + h*Dk;
    #pragma unroll
    for (int d = 0; d < 16; d++) e[d] = ep[d];
    #pragma unroll
    for (int r = 0; r < 8; r++) {
        int row = r0 + r;
        if (row >= Bsz*N1) break;
        int b = (row >= N1) ? 1 : 0;
        int n = row - b*N1;
        const float* q = qs[r] + h*Dk;
        float s = 0.f;
        #pragma unroll
        for (int d = 0; d < 16; d++) s += q[d]*e[d];
        d_QE[((size_t)(b*Hh + h)*N1 + n)*NBk + kb] = s;
    }
}

// ------------ Wo GEMM with fused split-K combine in the A-loader -------------
// Y = combine(PA)/CTX @ Wo^T + HG.  M=2050, Nc=K=128, 32x64 tiles.
__global__ void k_gemmC(const float* __restrict__ Bm, float* __restrict__ C)
{
    __shared__ __align__(16) float As[2][16][36];
    __shared__ __align__(16) float Bs[2][16][68];
    const int M = Bsz*N1;
    const int PST = Bsz*N1*Hh*PASTR;
    int tid = threadIdx.x;
    int tr = tid >> 4, tc = tid & 15;
    int r0 = blockIdx.y*32, c0 = blockIdx.x*64;
    int lr = tid >> 2;
    int lc = (tid & 3) * 4;
    bool aload = tid < 128;
    int ar = tid >> 2;
    int gr = r0 + ar, gc = c0 + lr;
    const float4 z4 = make_float4(0.f,0.f,0.f,0.f);
    bool valid = aload && gr < M;
    int abb = (gr >= N1) ? 1 : 0;
    int nn = gr - abb*N1;
    bool dense = (nn == 0) || (nn == Nn);
    size_t pbase = ((size_t)gr*Hh)*PASTR;
    auto fetchA = [&](int s) -> float4 {
        if (!valid) return z4;
        if (dense) return *(const float4*)(d_CTX + (size_t)gr*Dm + s*16 + lc);
        size_t pb = pbase + (size_t)s*PASTR;
        float4 p0 = *(const float4*)(d_PA + pb + lc);
        float4 p1 = *(const float4*)(d_PA + PST + pb + lc);
        float4 p2 = *(const float4*)(d_PA + 2*PST + pb + lc);
        float l = d_PA[pb+16] + d_PA[PST+pb+16] + d_PA[2*PST+pb+16];
        float inv = __fdividef(1.f, l);
        return make_float4((p0.x+p1.x+p2.x)*inv, (p0.y+p1.y+p2.y)*inv,
                           (p0.z+p1.z+p2.z)*inv, (p0.w+p1.w+p2.w)*inv);
    };
    float4 va = fetchA(0);
    float4 vb = *(const float4*)(Bm + (size_t)gc*Dm + lc);
    if (aload) {
        As[0][lc+0][ar]=va.x; As[0][lc+1][ar]=va.y; As[0][lc+2][ar]=va.z; As[0][lc+3][ar]=va.w;
    }
    Bs[0][lc+0][lr]=vb.x; Bs[0][lc+1][lr]=vb.y; Bs[0][lc+2][lr]=vb.z; Bs[0][lc+3][lr]=vb.w;
    __syncthreads();
    float acc[2][4] = {};
    #pragma unroll
    for (int s = 0; s < 8; s++) {
        int cur = s & 1;
        if (s < 7) {
            va = fetchA(s+1);
            vb = *(const float4*)(Bm + (size_t)gc*Dm + (s+1)*16 + lc);
        }
        #pragma unroll
        for (int k = 0; k < 16; k++) {
            float2 a2 = *(const float2*)&As[cur][k][tr*2];
            float4 b4 = *(const float4*)&Bs[cur][k][tc*4];
            acc[0][0] += a2.x*b4.x; acc[0][1] += a2.x*b4.y;
            acc[0][2] += a2.x*b4.z; acc[0][3] += a2.x*b4.w;
            acc[1][0] += a2.y*b4.x; acc[1][1] += a2.y*b4.y;
            acc[1][2] += a2.y*b4.z; acc[1][3] += a2.y*b4.w;
        }
        if (s < 7) {
            int nxt = cur ^ 1;
            if (aload) {
                As[nxt][lc+0][ar]=va.x; As[nxt][lc+1][ar]=va.y; As[nxt][lc+2][ar]=va.z; As[nxt][lc+3][ar]=va.w;
            }
            Bs[nxt][lc+0][lr]=vb.x; Bs[nxt][lc+1][lr]=vb.y; Bs[nxt][lc+2][lr]=vb.z; Bs[nxt][lc+3][lr]=vb.w;
            __syncthreads();
        }
    }
    int c = c0 + tc*4;
    #pragma unroll
    for (int i = 0; i < 2; i++) {
        int r = r0 + tr*2 + i;
        if (r >= M) continue;
        float4 rv = *(const float4*)(d_HG + (size_t)r*Dm + c);
        *(float4*)(C + (size_t)r*Dm + c) =
            make_float4(acc[i][0]+rv.x, acc[i][1]+rv.y, acc[i][2]+rv.z, acc[i][3]+rv.w);
    }
}

// --------- W1 GEMM: A = instancenorm(Y) on the fly (stats from PS partials) --
// T1 = relu(A @ W1^T + b1).  64x64 tiles, K=Dm.
__global__ void k_gemmW1(const float* __restrict__ Bm, const float* __restrict__ bias,
                         const float* __restrict__ n1w, const float* __restrict__ n1b,
                         float* __restrict__ C)
{
    __shared__ __align__(16) float As[2][16][68];
    __shared__ __align__(16) float Bs[2][16][68];
    __shared__ float smu[2][Dm], ssc[2][Dm], ssh[Dm];
    const int M = Bsz*N1;
    int tid = threadIdx.x;
    {   // precompute per-column stats for both batches (256 threads = 2x128)
        int b = tid >> 7, d = tid & 127;
        float S1 = 0.f, S2 = 0.f;
        #pragma unroll
        for (int t = 0; t < NCH; t++) {
            S1 += d_PS1[(b*NCH + t)*Dm + d];
            S2 += d_PS2[(b*NCH + t)*Dm + d];
        }
        float mu = S1 * (1.f/N1);
        smu[b][d] = mu;
        ssc[b][d] = rsqrtf(S2*(1.f/N1) - mu*mu + EPSf) * n1w[d];
        if (tid < Dm) ssh[tid] = n1b[tid];
    }
    __syncthreads();
    int tr = tid >> 4, tc = tid & 15;
    int r0 = blockIdx.y*64, c0 = blockIdx.x*64;
    int lr = tid >> 2;
    int lc = (tid & 3) * 4;
    int gr = r0 + lr, gc = c0 + lr;
    const float4 z4 = make_float4(0.f,0.f,0.f,0.f);
    int abb = (gr >= N1) ? 1 : 0;
    auto fetchA = [&](int s) -> float4 {
        if (gr >= M) return z4;
        int d = s*16 + lc;
        float4 x = *(const float4*)(d_Y + (size_t)gr*Dm + d);
        return make_float4((x.x - smu[abb][d+0])*ssc[abb][d+0] + ssh[d+0],
                           (x.y - smu[abb][d+1])*ssc[abb][d+1] + ssh[d+1],
                           (x.z - smu[abb][d+2])*ssc[abb][d+2] + ssh[d+2],
                           (x.w - smu[abb][d+3])*ssc[abb][d+3] + ssh[d+3]);
    };
    float4 va = fetchA(0);
    float4 vb = *(const float4*)(Bm + (size_t)gc*Dm + lc);
    As[0][lc+0][lr]=va.x; As[0][lc+1][lr]=va.y; As[0][lc+2][lr]=va.z; As[0][lc+3][lr]=va.w;
    Bs[0][lc+0][lr]=vb.x; Bs[0][lc+1][lr]=vb.y; Bs[0][lc+2][lr]=vb.z; Bs[0][lc+3][lr]=vb.w;
    __syncthreads();
    float acc[4][4] = {};
    #pragma unroll
    for (int s = 0; s < 8; s++) {
        int cur = s & 1;
        if (s < 7) {
            va = fetchA(s+1);
            vb = *(const float4*)(Bm + (size_t)gc*Dm + (s+1)*16 + lc);
        }
        #pragma unroll
        for (int k = 0; k < 16; k++) {
            float4 a4 = *(const float4*)&As[cur][k][tr*4];
            float4 b4 = *(const float4*)&Bs[cur][k][tc*4];
            float a[4] = {a4.x, a4.y, a4.z, a4.w};
            float bv[4] = {b4.x, b4.y, b4.z, b4.w};
            #pragma unroll
            for (int i = 0; i < 4; i++)
                #pragma unroll
                for (int j = 0; j < 4; j++) acc[i][j] += a[i]*bv[j];
        }
        if (s < 7) {
            int nxt = cur ^ 1;
            As[nxt][lc+0][lr]=va.x; As[nxt][lc+1][lr]=va.y; As[nxt][lc+2][lr]=va.z; As[nxt][lc+3][lr]=va.w;
            Bs[nxt][lc+0][lr]=vb.x; Bs[nxt][lc+1][lr]=vb.y; Bs[nxt][lc+2][lr]=vb.z; Bs[nxt][lc+3][lr]=vb.w;
            __syncthreads();
        }
    }
    int c = c0 + tc*4;
    float4 bz = *(const float4*)(bias + c);
    #pragma unroll
    for (int i = 0; i < 4; i++) {
        int r = r0 + tr*4 + i;
        if (r >= M) continue;
        *(float4*)(C + (size_t)r*Dff + c) =
            make_float4(fmaxf(acc[i][0]+bz.x, 0.f), fmaxf(acc[i][1]+bz.y, 0.f),
                        fmaxf(acc[i][2]+bz.z, 0.f), fmaxf(acc[i][3]+bz.w, 0.f));
    }
}

// --------- W2 GEMM: T2 = T1@W2^T + b2 + instancenorm(Y) residual -------------
// 32x64 tiles, K=Dff.  Stats from PS partials (smem precompute).
__global__ void k_gemmW2(const float* __restrict__ Bm, const float* __restrict__ bias,
                         const float* __restrict__ n1w, const float* __restrict__ n1b,
                         float* __restrict__ C)
{
    __shared__ __align__(16) float As[2][16][36];
    __shared__ __align__(16) float Bs[2][16][68];
    __shared__ float smu[2][Dm], ssc[2][Dm], ssh[Dm];
    const int M = Bsz*N1;
    int tid = threadIdx.x;
    {
        int b = tid >> 7, d = tid & 127;
        float S1 = 0.f, S2 = 0.f;
        #pragma unroll
        for (int t = 0; t < NCH; t++) {
            S1 += d_PS1[(b*NCH + t)*Dm + d];
            S2 += d_PS2[(b*NCH + t)*Dm + d];
        }
        float mu = S1 * (1.f/N1);
        smu[b][d] = mu;
        ssc[b][d] = rsqrtf(S2*(1.f/N1) - mu*mu + EPSf) * n1w[d];
        if (tid < Dm) ssh[tid] = n1b[tid];
    }
    __syncthreads();
    int tr = tid >> 4, tc = tid & 15;
    int r0 = blockIdx.y*32, c0 = blockIdx.x*64;
    int lr = tid >> 2;
    int lc = (tid & 3) * 4;
    bool aload = tid < 128;
    int ar = tid >> 2;
    int gr = r0 + ar, gc = c0 + lr;
    const float4 z4 = make_float4(0.f,0.f,0.f,0.f);
    float4 va = (aload && gr < M) ? *(const float4*)(d_T1 + (size_t)gr*Dff + lc) : z4;
    float4 vb = *(const float4*)(Bm + (size_t)gc*Dff + lc);
    if (aload) {
        As[0][lc+0][ar]=va.x; As[0][lc+1][ar]=va.y; As[0][lc+2][ar]=va.z; As[0][lc+3][ar]=va.w;
    }
    Bs[0][lc+0][lr]=vb.x; Bs[0][lc+1][lr]=vb.y; Bs[0][lc+2][lr]=vb.z; Bs[0][lc+3][lr]=vb.w;
    __syncthreads();
    float acc[2][4] = {};
    const int S = Dff >> 4;
    for (int s = 0; s < S; s++) {
        int cur = s & 1;
        if (s + 1 < S) {
            va = (aload && gr < M) ? *(const float4*)(d_T1 + (size_t)gr*Dff + (s+1)*16 + lc) : z4;
            vb = *(const float4*)(Bm + (size_t)gc*Dff + (s+1)*16 + lc);
        }
        #pragma unroll
        for (int k = 0; k < 16; k++) {
            float2 a2 = *(const float2*)&As[cur][k][tr*2];
            float4 b4 = *(const float4*)&Bs[cur][k][tc*4];
            acc[0][0] += a2.x*b4.x; acc[0][1] += a2.x*b4.y;
            acc[0][2] += a2.x*b4.z; acc[0][3] += a2.x*b4.w;
            acc[1][0] += a2.y*b4.x; acc[1][1] += a2.y*b4.y;
            acc[1][2] += a2.y*b4.z; acc[1][3] += a2.y*b4.w;
        }
        if (s + 1 < S) {
            int nxt = cur ^ 1;
            if (aload) {
                As[nxt][lc+0][ar]=va.x; As[nxt][lc+1][ar]=va.y; As[nxt][lc+2][ar]=va.z; As[nxt][lc+3][ar]=va.w;
            }
            Bs[nxt][lc+0][lr]=vb.x; Bs[nxt][lc+1][lr]=vb.y; Bs[nxt][lc+2][lr]=vb.z; Bs[nxt][lc+3][lr]=vb.w;
            __syncthreads();
        }
    }
    int c = c0 + tc*4;
    float4 bz = *(const float4*)(bias + c);
    #pragma unroll
    for (int i = 0; i < 2; i++) {
        int r = r0 + tr*2 + i;
        if (r >= M) continue;
        int bb = (r >= N1) ? 1 : 0;
        float4 x = *(const float4*)(d_Y + (size_t)r*Dm + c);
        *(float4*)(C + (size_t)r*Dm + c) = make_float4(
            acc[i][0]+bz.x + (x.x - smu[bb][c+0])*ssc[bb][c+0] + ssh[c+0],
            acc[i][1]+bz.y + (x.y - smu[bb][c+1])*ssc[bb][c+1] + ssh[c+1],
            acc[i][2]+bz.z + (x.z - smu[bb][c+2])*ssc[bb][c+2] + ssh[c+2],
            acc[i][3]+bz.w + (x.w - smu[bb][c+3])*ssc[bb][c+3] + ssh[c+3]);
    }
}

// ------------------------- sparse attention, split-K + fused dense -----------
__device__ __forceinline__ void attn_word20(unsigned word, int base,
    const float4 q4[4], float cqx, float cqy,
    const float (*Ks)[20], const float (*Vs)[20],
    const float* ckx, const float* cky, const float* qerow,
    float& lrun, float acc[16])
{
    while (word) {
        int mm = base + (__ffs((int)word) - 1);
        word &= word - 1u;
        const float4* kp = (const float4*)Ks[mm];
        float4 k0 = kp[0], k1 = kp[1], k2 = kp[2], k3 = kp[3];
        float s = q4[0].x*k0.x + q4[0].y*k0.y + q4[0].z*k0.z + q4[0].w*k0.w
                + q4[1].x*k1.x + q4[1].y*k1.y + q4[1].z*k1.z + q4[1].w*k1.w
                + q4[2].x*k2.x + q4[2].y*k2.y + q4[2].z*k2.z + q4[2].w*k2.w
                + q4[3].x*k3.x + q4[3].y*k3.y + q4[3].z*k3.z + q4[3].w*k3.w;
        float dx = cqx - ckx[mm], dy = cqy - cky[mm];
        float dist = sqrtf(dx*dx + dy*dy);
        int bk = (int)(dist * 32.f); if (bk > 31) bk = 31;
        float p = __expf(s*SCALEf + qerow[bk]);
        lrun += p;
        const float4* vp = (const float4*)Vs[mm];
        float4 v0 = vp[0], v1 = vp[1], v2 = vp[2], v3 = vp[3];
        acc[ 0] += p*v0.x; acc[ 1] += p*v0.y; acc[ 2] += p*v0.z; acc[ 3] += p*v0.w;
        acc[ 4] += p*v1.x; acc[ 5] += p*v1.y; acc[ 6] += p*v1.z; acc[ 7] += p*v1.w;
        acc[ 8] += p*v2.x; acc[ 9] += p*v2.y; acc[10] += p*v2.z; acc[11] += p*v2.w;
        acc[12] += p*v3.x; acc[13] += p*v3.y; acc[14] += p*v3.z; acc[15] += p*v3.w;
    }
}

// grid (25, Hh, Bsz), 128 threads. x<24: sparse (qtile=x/3, kseg=x%3).
// x==24: dense rows {0, Nn} (64 threads each).
__global__ void k_attn(const float* __restrict__ coords)
{
    __shared__ float Ks[128][20];
    __shared__ float Vs[128][20];
    __shared__ float ckx[128], cky[128];
    __shared__ float qes[128][33];
    __shared__ float pw[4][17];
    int b = blockIdx.z, h = blockIdx.y;
    int x = blockIdx.x;
    int tid = threadIdx.x;
    const size_t hb = (size_t)(b*Hh + h)*N1;

    if (x == 24) {   // ---- dense rows ----
        int sub = tid >> 6, st = tid & 63;
        int lane = tid & 31, w = tid >> 5;
        int n = sub ? Nn : 0;
        float q[16];
        const float4* qp = (const float4*)(d_Q + (hb + n)*Dk);
        #pragma unroll
        for (int i = 0; i < 4; i++) {
            float4 v = qp[i];
            q[i*4+0]=v.x; q[i*4+1]=v.y; q[i*4+2]=v.z; q[i*4+3]=v.w;
        }
        float cqx = 0.f, cqy = 0.f;
        if (n < Nn) { cqx = coords[(b*Nn+n)*2]; cqy = coords[(b*Nn+n)*2+1]; }
        const float* qerow = d_QE + (hb + n)*NBk;
        float l = 0.f, acc[16];
        #pragma unroll
        for (int d = 0; d < 16; d++) acc[d] = 0.f;
        const float* Kt = d_Kb + hb*Dk;
        const float* Vt = d_Vb + hb*Dk;
        for (int mk = st; mk < N1; mk += 64) {
            const float4* kp = (const float4*)(Kt + (size_t)mk*Dk);
            float s = 0.f;
            #pragma unroll
            for (int i = 0; i < 4; i++) {
                float4 kv = kp[i];
                s += q[i*4+0]*kv.x + q[i*4+1]*kv.y + q[i*4+2]*kv.z + q[i*4+3]*kv.w;
            }
            float cmx = 0.f, cmy = 0.f;
            if (mk < Nn) { cmx = coords[(b*Nn+mk)*2]; cmy = coords[(b*Nn+mk)*2+1]; }
            float dx = cqx - cmx, dy = cqy - cmy;
            float dist = sqrtf(dx*dx + dy*dy);
            int bk = (int)(dist * 32.f); if (bk > 31) bk = 31;
            float p = __expf(s*SCALEf + qerow[bk]);
            l += p;
            const float4* vp = (const float4*)(Vt + (size_t)mk*Dk);
            #pragma unroll
            for (int i = 0; i < 4; i++) {
                float4 vv = vp[i];
                acc[i*4+0] += p*vv.x; acc[i*4+1] += p*vv.y;
                acc[i*4+2] += p*vv.z; acc[i*4+3] += p*vv.w;
            }
        }
        #pragma unroll
        for (int o = 16; o; o >>= 1) {
            l += __shfl_xor_sync(0xffffffffu, l, o);
            #pragma unroll
            for (int d = 0; d < 16; d++) acc[d] += __shfl_xor_sync(0xffffffffu, acc[d], o);
        }
        if (lane == 0) {
            #pragma unroll
            for (int d = 0; d < 16; d++) pw[w][d] = acc[d];
            pw[w][16] = l;
        }
        __syncthreads();
        if (tid == 0 || tid == 64) {
            int w0 = sub*2;
            float L = pw[w0][16] + pw[w0+1][16];
            float inv = 1.f / L;
            float* o = d_CTX + ((size_t)(b*N1 + n))*Dm + h*Dk;
            #pragma unroll
            for (int d = 0; d < 16; d++) o[d] = (pw[w0][d] + pw[w0+1][d]) * inv;
        }
        return;
    }

    // ---- sparse split-K ----
    int qt = x / 3, kseg = x % 3;
    int n = qt*128 + tid;              // 0..1023
    bool qv = (n != 0);                // row 0 is dense
    float4 q4[4];
    float cqx = 0.f, cqy = 0.f, lrun = 0.f;
    float acc[16];
    #pragma unroll
    for (int d = 0; d < 16; d++) acc[d] = 0.f;
    const unsigned* rowadj = d_ADJ + (size_t)(b*N1 + n)*AW;
    {
        const float4* qp = (const float4*)(d_Q + (hb + n)*Dk);
        #pragma unroll
        for (int i = 0; i < 4; i++) q4[i] = qp[i];
        cqx = coords[(b*Nn+n)*2]; cqy = coords[(b*Nn+n)*2+1];
        const float4* qep = (const float4*)(d_QE + (hb + n)*NBk);
        #pragma unroll
        for (int i = 0; i < 8; i++) {
            float4 v = qep[i];
            qes[tid][i*4+0]=v.x; qes[tid][i*4+1]=v.y;
            qes[tid][i*4+2]=v.z; qes[tid][i*4+3]=v.w;
        }
    }
    for (int kt = kseg*3; kt < kseg*3 + 3; kt++) {
        int m0 = kt*128;
        int tlen = N1 - m0; if (tlen > 128) tlen = 128;
        const float4* Kt = (const float4*)(d_Kb + (hb + m0)*Dk);
        const float4* Vt = (const float4*)(d_Vb + (hb + m0)*Dk);
        __syncthreads();
        #pragma unroll
        for (int i = 0; i < 4; i++) {
            int f = tid + i*128;
            int row = f >> 2, j = (f & 3)*4;
            if (row < tlen) {
                *(float4*)&Ks[row][j] = Kt[f];
                *(float4*)&Vs[row][j] = Vt[f];
            }
        }
        if (tid < tlen) {
            int m = m0 + tid;
            if (m < Nn) { ckx[tid] = coords[(b*Nn+m)*2]; cky[tid] = coords[(b*Nn+m)*2+1]; }
            else        { ckx[tid] = 0.f; cky[tid] = 0.f; }
        }
        __syncthreads();
        if (!qv) continue;
        int wb = m0 >> 5;
        unsigned w0 = rowadj[wb];
        unsigned w1 = (wb+1 < AW) ? rowadj[wb+1] : 0u;
        unsigned w2 = (wb+2 < AW) ? rowadj[wb+2] : 0u;
        unsigned w3 = (wb+3 < AW) ? rowadj[wb+3] : 0u;
        attn_word20(w0,  0, q4, cqx, cqy, Ks, Vs, ckx, cky, qes[tid], lrun, acc);
        attn_word20(w1, 32, q4, cqx, cqy, Ks, Vs, ckx, cky, qes[tid], lrun, acc);
        attn_word20(w2, 64, q4, cqx, cqy, Ks, Vs, ckx, cky, qes[tid], lrun, acc);
        attn_word20(w3, 96, q4, cqx, cqy, Ks, Vs, ckx, cky, qes[tid], lrun, acc);
    }
    if (qv) {
        size_t base = ((size_t)kseg*Bsz*N1 + (size_t)b*N1 + n)*Hh + h;
        float* pa = d_PA + base*PASTR;
        *(float4*)(pa+ 0) = make_float4(acc[ 0], acc[ 1], acc[ 2], acc[ 3]);
        *(float4*)(pa+ 4) = make_float4(acc[ 4], acc[ 5], acc[ 6], acc[ 7]);
        *(float4*)(pa+ 8) = make_float4(acc[ 8], acc[ 9], acc[10], acc[11]);
        *(float4*)(pa+12) = make_float4(acc[12], acc[13], acc[14], acc[15]);
        pa[16] = lrun;
    }
}

// ------------------------- instance norm: stats (partials) -------------------
__global__ void k_istat(const float* __restrict__ src)
{
    __shared__ float s1[2][Dm], s2[2][Dm];
    int b = blockIdx.x, z = blockIdx.y;
    int d = threadIdx.x & 127, g = threadIdx.x >> 7;
    int nend = z*64 + 64; if (nend > N1) nend = N1;
    const float* p = src + (size_t)b*N1*Dm + d;
    float a = 0.f, qq = 0.f;
    for (int n = z*64 + g; n < nend; n += 2) {
        float x = p[(size_t)n*Dm];
        a += x; qq += x*x;
    }
    s1[g][d] = a; s2[g][d] = qq;
    __syncthreads();
    if (g == 0) {
        d_PS1[(b*NCH + z)*Dm + d] = s1[0][d] + s1[1][d];
        d_PS2[(b*NCH + z)*Dm + d] = s2[0][d] + s2[1][d];
    }
}

// ------------------------- instance norm apply: T2 -> HG ---------------------
// grid (Bsz, 4, 8), 1024 threads. Also g += mean(out_h), POOL += mean(out_h).
__global__ void k_iapply(const float* __restrict__ src, float* __restrict__ dst,
                         const float* __restrict__ w, const float* __restrict__ bb)
{
    int b  = blockIdx.x;
    int dl = threadIdx.x & 31;
    int g  = threadIdx.x >> 5;
    int d  = blockIdx.y*32 + dl;
    int z  = blockIdx.z;
    float S1 = 0.f, S2 = 0.f;
    #pragma unroll
    for (int t = 0; t < NCH; t++) {
        S1 += d_PS1[(b*NCH + t)*Dm + d];
        S2 += d_PS2[(b*NCH + t)*Dm + d];
    }
    float mu  = S1 * (1.f/N1);
    float var = S2 * (1.f/N1) - mu*mu;
    float sc  = rsqrtf(var + EPSf) * w[d];
    float sh  = bb[d];
    const float* p = src + (size_t)b*N1*Dm + d;
    float* o = dst + (size_t)b*N1*Dm + d;
    float mo = ((S1 - p[(size_t)Nn*Dm])*(1.f/Nn) - mu)*sc + sh;
    int n0 = z*128, n1 = (z == 7) ? N1 : (z+1)*128;
    for (int n = n0 + g; n < n1; n += 32) {
        float val = (p[(size_t)n*Dm] - mu)*sc + sh;
        if (n == Nn) val += mo;
        o[(size_t)n*Dm] = val;
    }
    if (z == 7 && g == 0) d_POOL[b*Dm + d] += mo;
}

// ------------------------- final GEMM: out = (h + pool/3) @ outW^T + outb ----
__global__ void k_fgemm(const float* __restrict__ Bm, const float* __restrict__ bias,
                        float* __restrict__ out)
{
    __shared__ __align__(16) float As[2][16][68];
    __shared__ __align__(16) float Bs[2][16][68];
    int tid = threadIdx.x;
    int tr = tid >> 4, tc = tid & 15;
    int r0 = blockIdx.y*64, c0 = blockIdx.x*64;
    int lr = tid >> 2;
    int lc = (tid & 3) * 4;
    int gr = r0 + lr;
    int bb = gr >> 10, nn = gr & 1023;
    const float* Arow = d_HG + ((size_t)bb*N1 + nn)*Dm;
    const float* Prow = d_POOL + bb*Dm;
    int gc = c0 + lr;
    if (blockIdx.x == 0 && blockIdx.y == 0 && tid < Bsz*Dm)
        out[Bsz*Nn*Dm + tid] = d_POOL[tid] * (1.f/3.f);
    float4 va, vb;
    {
        float4 hv = *(const float4*)(Arow + lc);
        float4 pv = *(const float4*)(Prow + lc);
        va = make_float4(hv.x + pv.x*(1.f/3.f), hv.y + pv.y*(1.f/3.f),
                         hv.z + pv.z*(1.f/3.f), hv.w + pv.w*(1.f/3.f));
        vb = *(const float4*)(Bm + (size_t)gc*Dm + lc);
    }
    As[0][lc+0][lr]=va.x; As[0][lc+1][lr]=va.y; As[0][lc+2][lr]=va.z; As[0][lc+3][lr]=va.w;
    Bs[0][lc+0][lr]=vb.x; Bs[0][lc+1][lr]=vb.y; Bs[0][lc+2][lr]=vb.z; Bs[0][lc+3][lr]=vb.w;
    __syncthreads();
    float acc[4][4] = {};
    #pragma unroll
    for (int s = 0; s < 8; s++) {
        int cur = s & 1;
        if (s < 7) {
            float4 hv = *(const float4*)(Arow + (s+1)*16 + lc);
            float4 pv = *(const float4*)(Prow + (s+1)*16 + lc);
            va = make_float4(hv.x + pv.x*(1.f/3.f), hv.y + pv.y*(1.f/3.f),
                             hv.z + pv.z*(1.f/3.f), hv.w + pv.w*(1.f/3.f));
            vb = *(const float4*)(Bm + (size_t)gc*Dm + (s+1)*16 + lc);
        }
        #pragma unroll
        for (int k = 0; k < 16; k++) {
            float4 a4 = *(const float4*)&As[cur][k][tr*4];
            float4 b4 = *(const float4*)&Bs[cur][k][tc*4];
            float a[4] = {a4.x, a4.y, a4.z, a4.w};
            float bv[4] = {b4.x, b4.y, b4.z, b4.w};
            #pragma unroll
            for (int i = 0; i < 4; i++)
                #pragma unroll
                for (int j = 0; j < 4; j++) acc[i][j] += a[i]*bv[j];
        }
        if (s < 7) {
            int nxt = cur ^ 1;
            As[nxt][lc+0][lr]=va.x; As[nxt][lc+1][lr]=va.y; As[nxt][lc+2][lr]=va.z; As[nxt][lc+3][lr]=va.w;
            Bs[nxt][lc+0][lr]=vb.x; Bs[nxt][lc+1][lr]=vb.y; Bs[nxt][lc+2][lr]=vb.z; Bs[nxt][lc+3][lr]=vb.w;
            __syncthreads();
        }
    }
    int c = c0 + tc*4;
    float4 bz = *(const float4*)(bias + c);
    #pragma unroll
    for (int i = 0; i < 4; i++) {
        int r = r0 + tr*4 + i;
        *(float4*)(out + (size_t)r*Dm + c) =
            make_float4(acc[i][0]+bz.x, acc[i][1]+bz.y, acc[i][2]+bz.z, acc[i][3]+bz.w);
    }
}

// ------------------------- host driver ---------------------------------------
extern "C" void kernel_launch(void* const* d_in, const int* in_sizes, int n_in,
                              void* d_out, int out_size)
{
    const float* coords = (const float*)d_in[0];
    const float* in_W   = (const float*)d_in[1];
    const float* in_b   = (const float*)d_in[2];
    const float* gnode  = (const float*)d_in[3];
    const float* Wq     = (const float*)d_in[4];
    const float* Wk     = (const float*)d_in[5];
    const float* Wv     = (const float*)d_in[6];
    const float* Wo     = (const float*)d_in[7];
    const float* emb    = (const float*)d_in[8];
    const float* W1     = (const float*)d_in[9];
    const float* b1     = (const float*)d_in[10];
    const float* W2     = (const float*)d_in[11];
    const float* b2     = (const float*)d_in[12];
    const float* n1w    = (const float*)d_in[13];
    const float* n1b    = (const float*)d_in[14];
    const float* n2w    = (const float*)d_in[15];
    const float* n2b    = (const float*)d_in[16];
    const float* outW   = (const float*)d_in[17];
    const float* outb   = (const float*)d_in[18];
    float* out = (float*)d_out;

    float *HG, *Y, *T1, *T2;
    cudaGetSymbolAddress((void**)&HG,  d_HG);
    cudaGetSymbolAddress((void**)&Y,   d_Y);
    cudaGetSymbolAddress((void**)&T1,  d_T1);
    cudaGetSymbolAddress((void**)&T2,  d_T2);

    const int Mall = Bsz*N1;  // 2050

    k_input<<<(Bsz*N1*Dm + 255)/256, 256>>>(coords, in_W, in_b, gnode);
    k_colmean<<<Bsz, 1024>>>();                            // layer-0 g update

    for (int l = 0; l < 3; l++) {
        k_par1<<<983, 256>>>(Wq + (size_t)l*Dm*Dm, Wk + (size_t)l*Dm*Dm, Wv + (size_t)l*Dm*Dm);
        k_par2<<<769, 256>>>(emb + (size_t)l*NBk*Dm);
        { dim3 ga(25, Hh, Bsz); k_attn<<<ga, 128>>>(coords); }

        { dim3 gq(Dm/64, (Mall + 31)/32);
          k_gemmC<<<gq, 256>>>(Wo + (size_t)l*Dm*Dm, Y); }
        { dim3 gs(Bsz, NCH); k_istat<<<gs, 256>>>(Y); }
        { dim3 g1(Dff/64, (Mall + 63)/64);
          k_gemmW1<<<g1, 256>>>(W1 + (size_t)l*Dff*Dm, b1 + l*Dff, n1w + l*Dm, n1b + l*Dm, T1); }
        { dim3 g2(Dm/64, (Mall + 31)/32);
          k_gemmW2<<<g2, 256>>>(W2 + (size_t)l*Dm*Dff, b2 + l*Dm, n1w + l*Dm, n1b + l*Dm, T2); }
        { dim3 gs(Bsz, NCH); k_istat<<<gs, 256>>>(T2); }
        { dim3 gi(Bsz, 4, 8); k_iapply<<<gi, 1024>>>(T2, HG, n2w + l*Dm, n2b + l*Dm); }
    }

    { dim3 ge(Dm/64, (Bsz*Nn)/64); k_fgemm<<<ge, 256>>>(outW, outb, out); }
}

// round 14
// speedup vs baseline: 1.6197x; 1.0288x over previous
#include <cuda_runtime.h>
#include <math_constants.h>
#include <math.h>

#define Bsz 2
#define Nn 1024
#define N1 1025
#define Dm 128
#define Hh 8
#define Dk 16
#define Dff 512
#define NBk 32
#define KNN 10
#define AW 33          // 33 x 32-bit words cover 1025 mask bits per row
#define EPSf 1e-5f
#define SCALEf 0.25f   // 1/sqrt(16)
#define NYT 65         // 32-row stat tiles over 2050 rows
#define PASTR 20       // split-K partial stride (floats), 16B-aligned

// ------------------------- persistent device scratch -------------------------
__device__ float    d_HG [Bsz*N1*Dm];     // state: rows 0..1023 = h, row 1024 = g
__device__ float    d_POOL[Bsz*Dm];
__device__ float    d_D2 [(size_t)Bsz*Nn*Nn];
__device__ unsigned d_ADJ[Bsz*N1*AW];
__device__ float    d_Q  [Bsz*Hh*N1*Dk];  // head-major: [b][h][n][dk]
__device__ float    d_Kb [Bsz*Hh*N1*Dk];
__device__ float    d_Vb [Bsz*Hh*N1*Dk];
__device__ float    d_CTX[Bsz*N1*Dm];
__device__ float    d_QE [Bsz*Hh*N1*NBk]; // head-major: [b][h][n][bucket]
__device__ float    d_Y  [Bsz*N1*Dm];
__device__ float    d_T1 [Bsz*N1*Dff];
__device__ float    d_T2 [Bsz*N1*Dm];
__device__ float    d_PS1[2*NYT*Dm], d_PS2[2*NYT*Dm];  // Y  col-stat partials
__device__ float    d_PT1[2*NYT*Dm], d_PT2[2*NYT*Dm];  // T2 col-stat partials
__device__ float    d_PA [3*Bsz*N1*Hh*PASTR];          // split-K partials

// ------------------------- input embedding + state init ----------------------
__global__ void k_input(const float* __restrict__ coords, const float* __restrict__ inW,
                        const float* __restrict__ inb, const float* __restrict__ gnode)
{
    int gid = blockIdx.x*blockDim.x + threadIdx.x;
    if (gid < Bsz*Dm) d_POOL[gid] = 0.f;
    if (gid >= Bsz*N1*Dm) return;
    int d = gid % Dm;
    int n = (gid / Dm) % N1;
    int b = gid / (Dm*N1);
    float v;
    if (n < Nn) {
        float x = coords[(b*Nn+n)*2+0];
        float y = coords[(b*Nn+n)*2+1];
        v = x*inW[d*2+0] + y*inW[d*2+1] + inb[d];
    } else {
        v = gnode[d];
    }
    d_HG[gid] = v;
}

// ------------------------- layer-0 g update: g += mean(h) --------------------
__global__ void k_colmean()
{
    __shared__ float red[8][Dm];
    int b = blockIdx.x;
    int d = threadIdx.x & 127;
    int g = threadIdx.x >> 7;
    const float* base = d_HG + (size_t)b*N1*Dm;
    float s = 0.f;
    for (int n = g; n < Nn; n += 8) s += base[n*Dm + d];
    red[g][d] = s;
    __syncthreads();
    if (g == 0) {
        float t = 0.f;
        #pragma unroll
        for (int i = 0; i < 8; i++) t += red[i][d];
        d_HG[(size_t)b*N1*Dm + Nn*Dm + d] += t * (1.f/Nn);
    }
}

// ===================== PAR1: D2 (self-norms) + QKV + ADJ-init =================
// grid: [0,272) d2 tiles, [272,470) qkv, [470,983) adjacency rows. 256 threads.
__global__ void k_par1(const float* __restrict__ wq, const float* __restrict__ wk,
                       const float* __restrict__ wv)
{
    __shared__ __align__(16) float As[2][16][68];
    __shared__ __align__(16) float Bs[2][16][68];
    __shared__ float rsq[64], csq[64];
    int bx = blockIdx.x;
    int tid = threadIdx.x;

    if (bx < 272) {        // ---------- D2 symmetric tile ----------
        int b = bx / 136;
        int x = bx % 136, bi = 0;
        while (x >= 16 - bi) { x -= 16 - bi; bi++; }
        int bj = bi + x;
        const float* A = d_HG + (size_t)b*N1*Dm;
        int tr = tid >> 4, tc = tid & 15;
        int r0 = bi*64, c0 = bj*64;
        int lr = tid >> 2, lc = (tid & 3)*4;
        float rn = 0.f, cn = 0.f;
        float4 va = *(const float4*)(A + (size_t)(r0+lr)*Dm + lc);
        float4 vb = *(const float4*)(A + (size_t)(c0+lr)*Dm + lc);
        rn += va.x*va.x + va.y*va.y + va.z*va.z + va.w*va.w;
        cn += vb.x*vb.x + vb.y*vb.y + vb.z*vb.z + vb.w*vb.w;
        As[0][lc+0][lr]=va.x; As[0][lc+1][lr]=va.y; As[0][lc+2][lr]=va.z; As[0][lc+3][lr]=va.w;
        Bs[0][lc+0][lr]=vb.x; Bs[0][lc+1][lr]=vb.y; Bs[0][lc+2][lr]=vb.z; Bs[0][lc+3][lr]=vb.w;
        __syncthreads();
        float acc[4][4] = {};
        #pragma unroll
        for (int s = 0; s < 8; s++) {
            int cur = s & 1;
            if (s < 7) {
                va = *(const float4*)(A + (size_t)(r0+lr)*Dm + (s+1)*16 + lc);
                vb = *(const float4*)(A + (size_t)(c0+lr)*Dm + (s+1)*16 + lc);
                rn += va.x*va.x + va.y*va.y + va.z*va.z + va.w*va.w;
                cn += vb.x*vb.x + vb.y*vb.y + vb.z*vb.z + vb.w*vb.w;
            }
            #pragma unroll
            for (int k = 0; k < 16; k++) {
                float4 a4 = *(const float4*)&As[cur][k][tr*4];
                float4 b4 = *(const float4*)&Bs[cur][k][tc*4];
                float a[4] = {a4.x, a4.y, a4.z, a4.w};
                float bv[4] = {b4.x, b4.y, b4.z, b4.w};
                #pragma unroll
                for (int i = 0; i < 4; i++)
                    #pragma unroll
                    for (int j = 0; j < 4; j++) acc[i][j] += a[i]*bv[j];
            }
            if (s < 7) {
                int nxt = cur ^ 1;
                As[nxt][lc+0][lr]=va.x; As[nxt][lc+1][lr]=va.y; As[nxt][lc+2][lr]=va.z; As[nxt][lc+3][lr]=va.w;
                Bs[nxt][lc+0][lr]=vb.x; Bs[nxt][lc+1][lr]=vb.y; Bs[nxt][lc+2][lr]=vb.z; Bs[nxt][lc+3][lr]=vb.w;
                __syncthreads();
            }
        }
        rn += __shfl_xor_sync(0xffffffffu, rn, 1);
        rn += __shfl_xor_sync(0xffffffffu, rn, 2);
        cn += __shfl_xor_sync(0xffffffffu, cn, 1);
        cn += __shfl_xor_sync(0xffffffffu, cn, 2);
        if ((tid & 3) == 0) { rsq[lr] = rn; csq[lr] = cn; }
        __syncthreads();
        float vals[4][4];
        #pragma unroll
        for (int i = 0; i < 4; i++) {
            int r = r0 + tr*4 + i;
            float sqr = rsq[tr*4 + i];
            float* orow = d_D2 + ((size_t)b*Nn + r)*Nn + c0 + tc*4;
            float o[4];
            #pragma unroll
            for (int j = 0; j < 4; j++) {
                int c = c0 + tc*4 + j;
                float v = sqr + csq[tc*4 + j] - 2.f*acc[i][j];
                o[j] = (r == c) ? CUDART_INF_F : v;
                vals[i][j] = o[j];
            }
            *(float4*)orow = make_float4(o[0], o[1], o[2], o[3]);
        }
        if (bi != bj) {
            #pragma unroll
            for (int j = 0; j < 4; j++) {
                int c = c0 + tc*4 + j;
                float* orow = d_D2 + ((size_t)b*Nn + c)*Nn + r0 + tr*4;
                *(float4*)orow = make_float4(vals[0][j], vals[1][j], vals[2][j], vals[3][j]);
            }
        }
        return;
    }

    if (bx < 470) {        // ---------- QKV GEMM ----------
        int idx = bx - 272;
        int sel = idx / 66, rem = idx % 66;
        const float* Bm = (sel == 0) ? wq : (sel == 1) ? wk : wv;
        float* C = (sel == 0) ? d_Q : (sel == 1) ? d_Kb : d_Vb;
        const int M = Bsz*N1;
        int tr = tid >> 4, tc = tid & 15;
        int r0 = (rem >> 1)*64, c0 = (rem & 1)*64;
        int lr = tid >> 2, lc = (tid & 3)*4;
        int gr = r0 + lr, gc = c0 + lr;
        const float4 z4 = make_float4(0.f,0.f,0.f,0.f);
        float4 va = (gr < M) ? *(const float4*)(d_HG + (size_t)gr*Dm + lc) : z4;
        float4 vb = *(const float4*)(Bm + (size_t)gc*Dm + lc);
        As[0][lc+0][lr]=va.x; As[0][lc+1][lr]=va.y; As[0][lc+2][lr]=va.z; As[0][lc+3][lr]=va.w;
        Bs[0][lc+0][lr]=vb.x; Bs[0][lc+1][lr]=vb.y; Bs[0][lc+2][lr]=vb.z; Bs[0][lc+3][lr]=vb.w;
        __syncthreads();
        float acc[4][4] = {};
        #pragma unroll
        for (int s = 0; s < 8; s++) {
            int cur = s & 1;
            if (s < 7) {
                va = (gr < M) ? *(const float4*)(d_HG + (size_t)gr*Dm + (s+1)*16 + lc) : z4;
                vb = *(const float4*)(Bm + (size_t)gc*Dm + (s+1)*16 + lc);
            }
            #pragma unroll
            for (int k = 0; k < 16; k++) {
                float4 a4 = *(const float4*)&As[cur][k][tr*4];
                float4 b4 = *(const float4*)&Bs[cur][k][tc*4];
                float a[4] = {a4.x, a4.y, a4.z, a4.w};
                float bv[4] = {b4.x, b4.y, b4.z, b4.w};
                #pragma unroll
                for (int i = 0; i < 4; i++)
                    #pragma unroll
                    for (int j = 0; j < 4; j++) acc[i][j] += a[i]*bv[j];
            }
            if (s < 7) {
                int nxt = cur ^ 1;
                As[nxt][lc+0][lr]=va.x; As[nxt][lc+1][lr]=va.y; As[nxt][lc+2][lr]=va.z; As[nxt][lc+3][lr]=va.w;
                Bs[nxt][lc+0][lr]=vb.x; Bs[nxt][lc+1][lr]=vb.y; Bs[nxt][lc+2][lr]=vb.z; Bs[nxt][lc+3][lr]=vb.w;
                __syncthreads();
            }
        }
        int c = c0 + tc*4;
        int h  = c >> 4;
        int dk = c & 15;
        #pragma unroll
        for (int i = 0; i < 4; i++) {
            int r = r0 + tr*4 + i;
            if (r >= M) continue;
            int bb = (r >= N1) ? 1 : 0;
            int n  = r - bb*N1;
            *(float4*)(C + ((size_t)(bb*Hh + h)*N1 + n)*Dk + dk) =
                make_float4(acc[i][0], acc[i][1], acc[i][2], acc[i][3]);
        }
        return;
    }

    // ---------- adjacency base pattern ----------
    {
        int row = (bx - 470)*4 + (tid >> 6);
        int t = tid & 63;
        if (row >= Bsz*N1 || t >= AW) return;
        int i = row % N1;
        int w = t;
        unsigned bits = 0u;
        #pragma unroll 4
        for (int q = 0; q < 32; q++) {
            int m = w*32 + q;
            if (m > Nn) break;
            bool on;
            if (i == Nn || m == Nn || i == m || i == 0 || m == 0) on = true;
            else {
                int di = i - m; if (di < 0) di = -di;
                on = ((i >> 7) == (m >> 7)) && (di <= 11);   // hier adjacency
            }
            if (on) bits |= 1u << q;
        }
        d_ADJ[row*AW + w] = bits;
    }
}

// ===================== PAR2: topk (2 warps/row) + qe (8 rows/block) ===========
// grid: [0,512) topk (4 rows x 2 warps), [512,769) qe (8 rows/block). 256 thr.
__global__ void k_par2(const float* __restrict__ emb)
{
    int bx = blockIdx.x;
    int tid = threadIdx.x;
    if (bx < 512) {        // ---------- exact top-10 kNN, 2 warps/row ----------
        __shared__ unsigned candK[2][4][2];
        __shared__ int      candJ[2][4][2];
        int wid  = tid >> 5;           // 0..7
        int lane = tid & 31;
        int rw   = wid >> 1;           // row within block 0..3
        int w    = wid & 1;            // column half 0/1
        int rowg = bx*4 + rw;          // 0..2047
        int b = rowg >> 10, i = rowg & 1023;
        const float* row = d_D2 + (size_t)rowg*Nn + w*512;
        unsigned uv[16];
        #pragma unroll
        for (int t = 0; t < 16; t++) {
            unsigned u = __float_as_uint(row[t*32 + lane]);
            uv[t] = (u & 0x80000000u) ? ~u : (u | 0x80000000u);
        }
        unsigned* adjb = d_ADJ + (size_t)b*N1*AW;
        for (int r = 0; r < KNN; r++) {
            unsigned m0 = min(uv[0], uv[4]),  m1 = min(uv[1], uv[5]);
            unsigned m2 = min(uv[2], uv[6]),  m3 = min(uv[3], uv[7]);
            m0 = min(m0, min(uv[8],  uv[12]));
            m1 = min(m1, min(uv[9],  uv[13]));
            m2 = min(m2, min(uv[10], uv[14]));
            m3 = min(m3, min(uv[11], uv[15]));
            unsigned mm = min(min(m0, m1), min(m2, m3));
            #pragma unroll
            for (int o = 16; o; o >>= 1)
                mm = min(mm, __shfl_xor_sync(0xffffffffu, mm, o));
            int lj = 0x7FFFFFFF;
            #pragma unroll
            for (int t = 0; t < 16; t++)
                if (uv[t] == mm) { lj = w*512 + t*32 + lane; break; }
            #pragma unroll
            for (int o = 16; o; o >>= 1)
                lj = min(lj, __shfl_xor_sync(0xffffffffu, lj, o));
            int pb = r & 1;
            if (lane == 0) { candK[pb][rw][w] = mm; candJ[pb][rw][w] = lj; }
            __syncthreads();
            unsigned k0 = candK[pb][rw][0], k1 = candK[pb][rw][1];
            int j0 = candJ[pb][rw][0], j1 = candJ[pb][rw][1];
            int bj;
            if (k0 < k1 || (k0 == k1 && j0 < j1)) bj = j0; else bj = j1;
            if (w == (bj >> 9)) {               // owning half clears the slot
                int jl = bj - w*512;
                if (lane == (jl & 31)) uv[jl >> 5] = 0xFFFFFFFFu;
            }
            if (w == 0 && lane == 0) {
                atomicOr(&adjb[i*AW + (bj >> 5)], 1u << (bj & 31));
                atomicOr(&adjb[bj*AW + (i >> 5)], 1u << (i & 31));
            }
        }
        return;
    }
    // ---------- qe: 8 rows per block ----------
    __shared__ float qs[8][Dm];
    int r0 = (bx - 512)*8;             // first global row (b*N1+n)
    if (tid < 128) {
        int hh = tid >> 4, dk = tid & 15;
        #pragma unroll
        for (int r = 0; r < 8; r++) {
            int row = r0 + r;
            if (row >= Bsz*N1) break;
            int b = (row >= N1) ? 1 : 0;
            int n = row - b*N1;
            qs[r][tid] = d_Q[((size_t)(b*Hh + hh)*N1 + n)*Dk + dk];
        }
    }
    __syncthreads();
    int h = tid >> 5, kb = tid & 31;
    float e[16];
    const float* ep = emb + kb*Dm + h*Dk;
    #pragma unroll
    for (int d = 0; d < 16; d++) e[d] = ep[d];
    #pragma unroll
    for (int r = 0; r < 8; r++) {
        int row = r0 + r;
        if (row >= Bsz*N1) break;
        int b = (row >= N1) ? 1 : 0;
        int n = row - b*N1;
        const float* q = qs[r] + h*Dk;
        float s = 0.f;
        #pragma unroll
        for (int d = 0; d < 16; d++) s += q[d]*e[d];
        d_QE[((size_t)(b*Hh + h)*N1 + n)*NBk + kb] = s;
    }
}

// ---- helper: block-tile column-stat reduction (32-row tiles, 256 threads) ---
// cs1/cs2: per-thread [batch][4] col partial sums. Writes PS[(ytile*2+b)*Dm+c].
__device__ __forceinline__ void tile_stats(float cs1[2][4], float cs2[2][4],
    int tr, int tc, int c, int ytile, float* PS1, float* PS2,
    float (*red1)[68], float (*red2)[68])
{
    #pragma unroll
    for (int pass = 0; pass < 2; pass++) {
        __syncthreads();
        #pragma unroll
        for (int j = 0; j < 4; j++) {
            red1[tr][tc*4+j] = cs1[pass][j];
            red2[tr][tc*4+j] = cs2[pass][j];
        }
        __syncthreads();
        #pragma unroll
        for (int o = 8; o; o >>= 1) {
            if (tr < o) {
                #pragma unroll
                for (int j = 0; j < 4; j++) {
                    red1[tr][tc*4+j] += red1[tr+o][tc*4+j];
                    red2[tr][tc*4+j] += red2[tr+o][tc*4+j];
                }
            }
            __syncthreads();
        }
        if (tr == 0) {
            #pragma unroll
            for (int j = 0; j < 4; j++) {
                PS1[(size_t)(ytile*2 + pass)*Dm + c + j] = red1[0][tc*4+j];
                PS2[(size_t)(ytile*2 + pass)*Dm + c + j] = red2[0][tc*4+j];
            }
        }
    }
}

// ------------ Wo GEMM: split-K combine + residual + Y stat partials ----------
// Y = combine(PA)/CTX @ Wo^T + HG.  M=2050, 32x64 tiles, grid (2, 65).
__global__ void k_gemmC(const float* __restrict__ Bm, float* __restrict__ C)
{
    __shared__ __align__(16) float As[2][16][36];
    __shared__ __align__(16) float Bs[2][16][68];
    __shared__ float red1[16][68], red2[16][68];
    const int M = Bsz*N1;
    const int PST = Bsz*N1*Hh*PASTR;
    int tid = threadIdx.x;
    int tr = tid >> 4, tc = tid & 15;
    int r0 = blockIdx.y*32, c0 = blockIdx.x*64;
    int lr = tid >> 2;
    int lc = (tid & 3) * 4;
    bool aload = tid < 128;
    int ar = tid >> 2;
    int gr = r0 + ar, gc = c0 + lr;
    const float4 z4 = make_float4(0.f,0.f,0.f,0.f);
    bool valid = aload && gr < M;
    int abb = (gr >= N1) ? 1 : 0;
    int nn = gr - abb*N1;
    bool dense = (nn == 0) || (nn == Nn);
    size_t pbase = ((size_t)gr*Hh)*PASTR;
    auto fetchA = [&](int s) -> float4 {
        if (!valid) return z4;
        if (dense) return *(const float4*)(d_CTX + (size_t)gr*Dm + s*16 + lc);
        size_t pb = pbase + (size_t)s*PASTR;
        float4 p0 = *(const float4*)(d_PA + pb + lc);
        float4 p1 = *(const float4*)(d_PA + PST + pb + lc);
        float4 p2 = *(const float4*)(d_PA + 2*PST + pb + lc);
        float l = d_PA[pb+16] + d_PA[PST+pb+16] + d_PA[2*PST+pb+16];
        float inv = __fdividef(1.f, l);
        return make_float4((p0.x+p1.x+p2.x)*inv, (p0.y+p1.y+p2.y)*inv,
                           (p0.z+p1.z+p2.z)*inv, (p0.w+p1.w+p2.w)*inv);
    };
    float4 va = fetchA(0);
    float4 vb = *(const float4*)(Bm + (size_t)gc*Dm + lc);
    if (aload) {
        As[0][lc+0][ar]=va.x; As[0][lc+1][ar]=va.y; As[0][lc+2][ar]=va.z; As[0][lc+3][ar]=va.w;
    }
    Bs[0][lc+0][lr]=vb.x; Bs[0][lc+1][lr]=vb.y; Bs[0][lc+2][lr]=vb.z; Bs[0][lc+3][lr]=vb.w;
    __syncthreads();
    float acc[2][4] = {};
    #pragma unroll
    for (int s = 0; s < 8; s++) {
        int cur = s & 1;
        if (s < 7) {
            va = fetchA(s+1);
            vb = *(const float4*)(Bm + (size_t)gc*Dm + (s+1)*16 + lc);
        }
        #pragma unroll
        for (int k = 0; k < 16; k++) {
            float2 a2 = *(const float2*)&As[cur][k][tr*2];
            float4 b4 = *(const float4*)&Bs[cur][k][tc*4];
            acc[0][0] += a2.x*b4.x; acc[0][1] += a2.x*b4.y;
            acc[0][2] += a2.x*b4.z; acc[0][3] += a2.x*b4.w;
            acc[1][0] += a2.y*b4.x; acc[1][1] += a2.y*b4.y;
            acc[1][2] += a2.y*b4.z; acc[1][3] += a2.y*b4.w;
        }
        if (s < 7) {
            int nxt = cur ^ 1;
            if (aload) {
                As[nxt][lc+0][ar]=va.x; As[nxt][lc+1][ar]=va.y; As[nxt][lc+2][ar]=va.z; As[nxt][lc+3][ar]=va.w;
            }
            Bs[nxt][lc+0][lr]=vb.x; Bs[nxt][lc+1][lr]=vb.y; Bs[nxt][lc+2][lr]=vb.z; Bs[nxt][lc+3][lr]=vb.w;
            __syncthreads();
        }
    }
    int c = c0 + tc*4;
    float cs1[2][4] = {{0,0,0,0},{0,0,0,0}};
    float cs2[2][4] = {{0,0,0,0},{0,0,0,0}};
    #pragma unroll
    for (int i = 0; i < 2; i++) {
        int r = r0 + tr*2 + i;
        if (r >= M) continue;
        int bb = (r >= N1) ? 1 : 0;
        float4 rv = *(const float4*)(d_HG + (size_t)r*Dm + c);
        float4 v = make_float4(acc[i][0]+rv.x, acc[i][1]+rv.y, acc[i][2]+rv.z, acc[i][3]+rv.w);
        *(float4*)(C + (size_t)r*Dm + c) = v;
        cs1[bb][0] += v.x; cs2[bb][0] += v.x*v.x;
        cs1[bb][1] += v.y; cs2[bb][1] += v.y*v.y;
        cs1[bb][2] += v.z; cs2[bb][2] += v.z*v.z;
        cs1[bb][3] += v.w; cs2[bb][3] += v.w*v.w;
    }
    tile_stats(cs1, cs2, tr, tc, c, blockIdx.y, d_PS1, d_PS2, red1, red2);
}

// --------- W1 GEMM: A = instancenorm(Y) on the fly (stats from PS partials) --
// T1 = relu(A @ W1^T + b1).  64x64 tiles, K=Dm.
__global__ void k_gemmW1(const float* __restrict__ Bm, const float* __restrict__ bias,
                         const float* __restrict__ n1w, const float* __restrict__ n1b,
                         float* __restrict__ C)
{
    __shared__ __align__(16) float As[2][16][68];
    __shared__ __align__(16) float Bs[2][16][68];
    __shared__ float smu[2][Dm], ssc[2][Dm], ssh[Dm];
    const int M = Bsz*N1;
    int tid = threadIdx.x;
    {   // precompute per-column stats for both batches (256 threads = 2x128)
        int b = tid >> 7, d = tid & 127;
        float S1 = 0.f, S2 = 0.f;
        for (int t = 0; t < NYT; t++) {
            S1 += d_PS1[(size_t)(t*2 + b)*Dm + d];
            S2 += d_PS2[(size_t)(t*2 + b)*Dm + d];
        }
        float mu = S1 * (1.f/N1);
        smu[b][d] = mu;
        ssc[b][d] = rsqrtf(S2*(1.f/N1) - mu*mu + EPSf) * n1w[d];
        if (tid < Dm) ssh[tid] = n1b[tid];
    }
    __syncthreads();
    int tr = tid >> 4, tc = tid & 15;
    int r0 = blockIdx.y*64, c0 = blockIdx.x*64;
    int lr = tid >> 2;
    int lc = (tid & 3) * 4;
    int gr = r0 + lr, gc = c0 + lr;
    const float4 z4 = make_float4(0.f,0.f,0.f,0.f);
    int abb = (gr >= N1) ? 1 : 0;
    auto fetchA = [&](int s) -> float4 {
        if (gr >= M) return z4;
        int d = s*16 + lc;
        float4 x = *(const float4*)(d_Y + (size_t)gr*Dm + d);
        return make_float4((x.x - smu[abb][d+0])*ssc[abb][d+0] + ssh[d+0],
                           (x.y - smu[abb][d+1])*ssc[abb][d+1] + ssh[d+1],
                           (x.z - smu[abb][d+2])*ssc[abb][d+2] + ssh[d+2],
                           (x.w - smu[abb][d+3])*ssc[abb][d+3] + ssh[d+3]);
    };
    float4 va = fetchA(0);
    float4 vb = *(const float4*)(Bm + (size_t)gc*Dm + lc);
    As[0][lc+0][lr]=va.x; As[0][lc+1][lr]=va.y; As[0][lc+2][lr]=va.z; As[0][lc+3][lr]=va.w;
    Bs[0][lc+0][lr]=vb.x; Bs[0][lc+1][lr]=vb.y; Bs[0][lc+2][lr]=vb.z; Bs[0][lc+3][lr]=vb.w;
    __syncthreads();
    float acc[4][4] = {};
    #pragma unroll
    for (int s = 0; s < 8; s++) {
        int cur = s & 1;
        if (s < 7) {
            va = fetchA(s+1);
            vb = *(const float4*)(Bm + (size_t)gc*Dm + (s+1)*16 + lc);
        }
        #pragma unroll
        for (int k = 0; k < 16; k++) {
            float4 a4 = *(const float4*)&As[cur][k][tr*4];
            float4 b4 = *(const float4*)&Bs[cur][k][tc*4];
            float a[4] = {a4.x, a4.y, a4.z, a4.w};
            float bv[4] = {b4.x, b4.y, b4.z, b4.w};
            #pragma unroll
            for (int i = 0; i < 4; i++)
                #pragma unroll
                for (int j = 0; j < 4; j++) acc[i][j] += a[i]*bv[j];
        }
        if (s < 7) {
            int nxt = cur ^ 1;
            As[nxt][lc+0][lr]=va.x; As[nxt][lc+1][lr]=va.y; As[nxt][lc+2][lr]=va.z; As[nxt][lc+3][lr]=va.w;
            Bs[nxt][lc+0][lr]=vb.x; Bs[nxt][lc+1][lr]=vb.y; Bs[nxt][lc+2][lr]=vb.z; Bs[nxt][lc+3][lr]=vb.w;
            __syncthreads();
        }
    }
    int c = c0 + tc*4;
    float4 bz = *(const float4*)(bias + c);
    #pragma unroll
    for (int i = 0; i < 4; i++) {
        int r = r0 + tr*4 + i;
        if (r >= M) continue;
        *(float4*)(C + (size_t)r*Dff + c) =
            make_float4(fmaxf(acc[i][0]+bz.x, 0.f), fmaxf(acc[i][1]+bz.y, 0.f),
                        fmaxf(acc[i][2]+bz.z, 0.f), fmaxf(acc[i][3]+bz.w, 0.f));
    }
}

// --------- W2 GEMM: T2 = T1@W2^T + b2 + inorm(Y) residual; T2 stat partials ---
// 32x64 tiles, K=Dff, grid (2, 65).
__global__ void k_gemmW2(const float* __restrict__ Bm, const float* __restrict__ bias,
                         const float* __restrict__ n1w, const float* __restrict__ n1b,
                         float* __restrict__ C)
{
    __shared__ __align__(16) float As[2][16][36];
    __shared__ __align__(16) float Bs[2][16][68];
    __shared__ float smu[2][Dm], ssc[2][Dm], ssh[Dm];
    __shared__ float red1[16][68], red2[16][68];
    const int M = Bsz*N1;
    int tid = threadIdx.x;
    {
        int b = tid >> 7, d = tid & 127;
        float S1 = 0.f, S2 = 0.f;
        for (int t = 0; t < NYT; t++) {
            S1 += d_PS1[(size_t)(t*2 + b)*Dm + d];
            S2 += d_PS2[(size_t)(t*2 + b)*Dm + d];
        }
        float mu = S1 * (1.f/N1);
        smu[b][d] = mu;
        ssc[b][d] = rsqrtf(S2*(1.f/N1) - mu*mu + EPSf) * n1w[d];
        if (tid < Dm) ssh[tid] = n1b[tid];
    }
    __syncthreads();
    int tr = tid >> 4, tc = tid & 15;
    int r0 = blockIdx.y*32, c0 = blockIdx.x*64;
    int lr = tid >> 2;
    int lc = (tid & 3) * 4;
    bool aload = tid < 128;
    int ar = tid >> 2;
    int gr = r0 + ar, gc = c0 + lr;
    const float4 z4 = make_float4(0.f,0.f,0.f,0.f);
    float4 va = (aload && gr < M) ? *(const float4*)(d_T1 + (size_t)gr*Dff + lc) : z4;
    float4 vb = *(const float4*)(Bm + (size_t)gc*Dff + lc);
    if (aload) {
        As[0][lc+0][ar]=va.x; As[0][lc+1][ar]=va.y; As[0][lc+2][ar]=va.z; As[0][lc+3][ar]=va.w;
    }
    Bs[0][lc+0][lr]=vb.x; Bs[0][lc+1][lr]=vb.y; Bs[0][lc+2][lr]=vb.z; Bs[0][lc+3][lr]=vb.w;
    __syncthreads();
    float acc[2][4] = {};
    const int S = Dff >> 4;
    for (int s = 0; s < S; s++) {
        int cur = s & 1;
        if (s + 1 < S) {
            va = (aload && gr < M) ? *(const float4*)(d_T1 + (size_t)gr*Dff + (s+1)*16 + lc) : z4;
            vb = *(const float4*)(Bm + (size_t)gc*Dff + (s+1)*16 + lc);
        }
        #pragma unroll
        for (int k = 0; k < 16; k++) {
            float2 a2 = *(const float2*)&As[cur][k][tr*2];
            float4 b4 = *(const float4*)&Bs[cur][k][tc*4];
            acc[0][0] += a2.x*b4.x; acc[0][1] += a2.x*b4.y;
            acc[0][2] += a2.x*b4.z; acc[0][3] += a2.x*b4.w;
            acc[1][0] += a2.y*b4.x; acc[1][1] += a2.y*b4.y;
            acc[1][2] += a2.y*b4.z; acc[1][3] += a2.y*b4.w;
        }
        if (s + 1 < S) {
            int nxt = cur ^ 1;
            if (aload) {
                As[nxt][lc+0][ar]=va.x; As[nxt][lc+1][ar]=va.y; As[nxt][lc+2][ar]=va.z; As[nxt][lc+3][ar]=va.w;
            }
            Bs[nxt][lc+0][lr]=vb.x; Bs[nxt][lc+1][lr]=vb.y; Bs[nxt][lc+2][lr]=vb.z; Bs[nxt][lc+3][lr]=vb.w;
            __syncthreads();
        }
    }
    int c = c0 + tc*4;
    float4 bz = *(const float4*)(bias + c);
    float cs1[2][4] = {{0,0,0,0},{0,0,0,0}};
    float cs2[2][4] = {{0,0,0,0},{0,0,0,0}};
    #pragma unroll
    for (int i = 0; i < 2; i++) {
        int r = r0 + tr*2 + i;
        if (r >= M) continue;
        int bb = (r >= N1) ? 1 : 0;
        float4 x = *(const float4*)(d_Y + (size_t)r*Dm + c);
        float4 v = make_float4(
            acc[i][0]+bz.x + (x.x - smu[bb][c+0])*ssc[bb][c+0] + ssh[c+0],
            acc[i][1]+bz.y + (x.y - smu[bb][c+1])*ssc[bb][c+1] + ssh[c+1],
            acc[i][2]+bz.z + (x.z - smu[bb][c+2])*ssc[bb][c+2] + ssh[c+2],
            acc[i][3]+bz.w + (x.w - smu[bb][c+3])*ssc[bb][c+3] + ssh[c+3]);
        *(float4*)(C + (size_t)r*Dm + c) = v;
        cs1[bb][0] += v.x; cs2[bb][0] += v.x*v.x;
        cs1[bb][1] += v.y; cs2[bb][1] += v.y*v.y;
        cs1[bb][2] += v.z; cs2[bb][2] += v.z*v.z;
        cs1[bb][3] += v.w; cs2[bb][3] += v.w*v.w;
    }
    tile_stats(cs1, cs2, tr, tc, c, blockIdx.y, d_PT1, d_PT2, red1, red2);
}

// ------------------------- sparse attention, split-K + fused dense -----------
__device__ __forceinline__ void attn_word20(unsigned word, int base,
    const float4 q4[4], float cqx, float cqy,
    const float (*Ks)[20], const float (*Vs)[20],
    const float* ckx, const float* cky, const float* qerow,
    float& lrun, float acc[16])
{
    while (word) {
        int mm = base + (__ffs((int)word) - 1);
        word &= word - 1u;
        const float4* kp = (const float4*)Ks[mm];
        float4 k0 = kp[0], k1 = kp[1], k2 = kp[2], k3 = kp[3];
        float s = q4[0].x*k0.x + q4[0].y*k0.y + q4[0].z*k0.z + q4[0].w*k0.w
                + q4[1].x*k1.x + q4[1].y*k1.y + q4[1].z*k1.z + q4[1].w*k1.w
                + q4[2].x*k2.x + q4[2].y*k2.y + q4[2].z*k2.z + q4[2].w*k2.w
                + q4[3].x*k3.x + q4[3].y*k3.y + q4[3].z*k3.z + q4[3].w*k3.w;
        float dx = cqx - ckx[mm], dy = cqy - cky[mm];
        float dist = sqrtf(dx*dx + dy*dy);
        int bk = (int)(dist * 32.f); if (bk > 31) bk = 31;
        float p = __expf(s*SCALEf + qerow[bk]);
        lrun += p;
        const float4* vp = (const float4*)Vs[mm];
        float4 v0 = vp[0], v1 = vp[1], v2 = vp[2], v3 = vp[3];
        acc[ 0] += p*v0.x; acc[ 1] += p*v0.y; acc[ 2] += p*v0.z; acc[ 3] += p*v0.w;
        acc[ 4] += p*v1.x; acc[ 5] += p*v1.y; acc[ 6] += p*v1.z; acc[ 7] += p*v1.w;
        acc[ 8] += p*v2.x; acc[ 9] += p*v2.y; acc[10] += p*v2.z; acc[11] += p*v2.w;
        acc[12] += p*v3.x; acc[13] += p*v3.y; acc[14] += p*v3.z; acc[15] += p*v3.w;
    }
}

// grid (25, Hh, Bsz), 128 threads. x<24: sparse (qtile=x/3, kseg=x%3).
// x==24: dense rows {0, Nn} (64 threads each).
__global__ void k_attn(const float* __restrict__ coords)
{
    __shared__ float Ks[128][20];
    __shared__ float Vs[128][20];
    __shared__ float ckx[128], cky[128];
    __shared__ float qes[128][33];
    __shared__ float pw[4][17];
    int b = blockIdx.z, h = blockIdx.y;
    int x = blockIdx.x;
    int tid = threadIdx.x;
    const size_t hb = (size_t)(b*Hh + h)*N1;

    if (x == 24) {   // ---- dense rows ----
        int sub = tid >> 6, st = tid & 63;
        int lane = tid & 31, w = tid >> 5;
        int n = sub ? Nn : 0;
        float q[16];
        const float4* qp = (const float4*)(d_Q + (hb + n)*Dk);
        #pragma unroll
        for (int i = 0; i < 4; i++) {
            float4 v = qp[i];
            q[i*4+0]=v.x; q[i*4+1]=v.y; q[i*4+2]=v.z; q[i*4+3]=v.w;
        }
        float cqx = 0.f, cqy = 0.f;
        if (n < Nn) { cqx = coords[(b*Nn+n)*2]; cqy = coords[(b*Nn+n)*2+1]; }
        const float* qerow = d_QE + (hb + n)*NBk;
        float l = 0.f, acc[16];
        #pragma unroll
        for (int d = 0; d < 16; d++) acc[d] = 0.f;
        const float* Kt = d_Kb + hb*Dk;
        const float* Vt = d_Vb + hb*Dk;
        for (int mk = st; mk < N1; mk += 64) {
            const float4* kp = (const float4*)(Kt + (size_t)mk*Dk);
            float s = 0.f;
            #pragma unroll
            for (int i = 0; i < 4; i++) {
                float4 kv = kp[i];
                s += q[i*4+0]*kv.x + q[i*4+1]*kv.y + q[i*4+2]*kv.z + q[i*4+3]*kv.w;
            }
            float cmx = 0.f, cmy = 0.f;
            if (mk < Nn) { cmx = coords[(b*Nn+mk)*2]; cmy = coords[(b*Nn+mk)*2+1]; }
            float dx = cqx - cmx, dy = cqy - cmy;
            float dist = sqrtf(dx*dx + dy*dy);
            int bk = (int)(dist * 32.f); if (bk > 31) bk = 31;
            float p = __expf(s*SCALEf + qerow[bk]);
            l += p;
            const float4* vp = (const float4*)(Vt + (size_t)mk*Dk);
            #pragma unroll
            for (int i = 0; i < 4; i++) {
                float4 vv = vp[i];
                acc[i*4+0] += p*vv.x; acc[i*4+1] += p*vv.y;
                acc[i*4+2] += p*vv.z; acc[i*4+3] += p*vv.w;
            }
        }
        #pragma unroll
        for (int o = 16; o; o >>= 1) {
            l += __shfl_xor_sync(0xffffffffu, l, o);
            #pragma unroll
            for (int d = 0; d < 16; d++) acc[d] += __shfl_xor_sync(0xffffffffu, acc[d], o);
        }
        if (lane == 0) {
            #pragma unroll
            for (int d = 0; d < 16; d++) pw[w][d] = acc[d];
            pw[w][16] = l;
        }
        __syncthreads();
        if (tid == 0 || tid == 64) {
            int w0 = sub*2;
            float L = pw[w0][16] + pw[w0+1][16];
            float inv = 1.f / L;
            float* o = d_CTX + ((size_t)(b*N1 + n))*Dm + h*Dk;
            #pragma unroll
            for (int d = 0; d < 16; d++) o[d] = (pw[w0][d] + pw[w0+1][d]) * inv;
        }
        return;
    }

    // ---- sparse split-K ----
    int qt = x / 3, kseg = x % 3;
    int n = qt*128 + tid;              // 0..1023
    bool qv = (n != 0);                // row 0 is dense
    float4 q4[4];
    float cqx = 0.f, cqy = 0.f, lrun = 0.f;
    float acc[16];
    #pragma unroll
    for (int d = 0; d < 16; d++) acc[d] = 0.f;
    const unsigned* rowadj = d_ADJ + (size_t)(b*N1 + n)*AW;
    {
        const float4* qp = (const float4*)(d_Q + (hb + n)*Dk);
        #pragma unroll
        for (int i = 0; i < 4; i++) q4[i] = qp[i];
        cqx = coords[(b*Nn+n)*2]; cqy = coords[(b*Nn+n)*2+1];
        const float4* qep = (const float4*)(d_QE + (hb + n)*NBk);
        #pragma unroll
        for (int i = 0; i < 8; i++) {
            float4 v = qep[i];
            qes[tid][i*4+0]=v.x; qes[tid][i*4+1]=v.y;
            qes[tid][i*4+2]=v.z; qes[tid][i*4+3]=v.w;
        }
    }
    for (int kt = kseg*3; kt < kseg*3 + 3; kt++) {
        int m0 = kt*128;
        int tlen = N1 - m0; if (tlen > 128) tlen = 128;
        const float4* Kt = (const float4*)(d_Kb + (hb + m0)*Dk);
        const float4* Vt = (const float4*)(d_Vb + (hb + m0)*Dk);
        __syncthreads();
        #pragma unroll
        for (int i = 0; i < 4; i++) {
            int f = tid + i*128;
            int row = f >> 2, j = (f & 3)*4;
            if (row < tlen) {
                *(float4*)&Ks[row][j] = Kt[f];
                *(float4*)&Vs[row][j] = Vt[f];
            }
        }
        if (tid < tlen) {
            int m = m0 + tid;
            if (m < Nn) { ckx[tid] = coords[(b*Nn+m)*2]; cky[tid] = coords[(b*Nn+m)*2+1]; }
            else        { ckx[tid] = 0.f; cky[tid] = 0.f; }
        }
        __syncthreads();
        if (!qv) continue;
        int wb = m0 >> 5;
        unsigned w0 = rowadj[wb];
        unsigned w1 = (wb+1 < AW) ? rowadj[wb+1] : 0u;
        unsigned w2 = (wb+2 < AW) ? rowadj[wb+2] : 0u;
        unsigned w3 = (wb+3 < AW) ? rowadj[wb+3] : 0u;
        attn_word20(w0,  0, q4, cqx, cqy, Ks, Vs, ckx, cky, qes[tid], lrun, acc);
        attn_word20(w1, 32, q4, cqx, cqy, Ks, Vs, ckx, cky, qes[tid], lrun, acc);
        attn_word20(w2, 64, q4, cqx, cqy, Ks, Vs, ckx, cky, qes[tid], lrun, acc);
        attn_word20(w3, 96, q4, cqx, cqy, Ks, Vs, ckx, cky, qes[tid], lrun, acc);
    }
    if (qv) {
        size_t base = ((size_t)kseg*Bsz*N1 + (size_t)b*N1 + n)*Hh + h;
        float* pa = d_PA + base*PASTR;
        *(float4*)(pa+ 0) = make_float4(acc[ 0], acc[ 1], acc[ 2], acc[ 3]);
        *(float4*)(pa+ 4) = make_float4(acc[ 4], acc[ 5], acc[ 6], acc[ 7]);
        *(float4*)(pa+ 8) = make_float4(acc[ 8], acc[ 9], acc[10], acc[11]);
        *(float4*)(pa+12) = make_float4(acc[12], acc[13], acc[14], acc[15]);
        pa[16] = lrun;
    }
}

// ------------------------- instance norm apply: T2 -> HG (via PT partials) ---
// grid (Bsz, 4, 8), 1024 threads. Also g += mean(out_h), POOL += mean(out_h).
__global__ void k_iapply(const float* __restrict__ src, float* __restrict__ dst,
                         const float* __restrict__ w, const float* __restrict__ bb)
{
    int b  = blockIdx.x;
    int dl = threadIdx.x & 31;
    int g  = threadIdx.x >> 5;
    int d  = blockIdx.y*32 + dl;
    int z  = blockIdx.z;
    float S1 = 0.f, S2 = 0.f;
    for (int t = 0; t < NYT; t++) {
        S1 += d_PT1[(size_t)(t*2 + b)*Dm + d];
        S2 += d_PT2[(size_t)(t*2 + b)*Dm + d];
    }
    float mu  = S1 * (1.f/N1);
    float var = S2 * (1.f/N1) - mu*mu;
    float sc  = rsqrtf(var + EPSf) * w[d];
    float sh  = bb[d];
    const float* p = src + (size_t)b*N1*Dm + d;
    float* o = dst + (size_t)b*N1*Dm + d;
    float mo = ((S1 - p[(size_t)Nn*Dm])*(1.f/Nn) - mu)*sc + sh;
    int n0 = z*128, n1 = (z == 7) ? N1 : (z+1)*128;
    for (int n = n0 + g; n < n1; n += 32) {
        float val = (p[(size_t)n*Dm] - mu)*sc + sh;
        if (n == Nn) val += mo;
        o[(size_t)n*Dm] = val;
    }
    if (z == 7 && g == 0) d_POOL[b*Dm + d] += mo;
}

// ------------------------- final GEMM: out = (h + pool/3) @ outW^T + outb ----
__global__ void k_fgemm(const float* __restrict__ Bm, const float* __restrict__ bias,
                        float* __restrict__ out)
{
    __shared__ __align__(16) float As[2][16][68];
    __shared__ __align__(16) float Bs[2][16][68];
    int tid = threadIdx.x;
    int tr = tid >> 4, tc = tid & 15;
    int r0 = blockIdx.y*64, c0 = blockIdx.x*64;
    int lr = tid >> 2;
    int lc = (tid & 3) * 4;
    int gr = r0 + lr;
    int bb = gr >> 10, nn = gr & 1023;
    const float* Arow = d_HG + ((size_t)bb*N1 + nn)*Dm;
    const float* Prow = d_POOL + bb*Dm;
    int gc = c0 + lr;
    if (blockIdx.x == 0 && blockIdx.y == 0 && tid < Bsz*Dm)
        out[Bsz*Nn*Dm + tid] = d_POOL[tid] * (1.f/3.f);
    float4 va, vb;
    {
        float4 hv = *(const float4*)(Arow + lc);
        float4 pv = *(const float4*)(Prow + lc);
        va = make_float4(hv.x + pv.x*(1.f/3.f), hv.y + pv.y*(1.f/3.f),
                         hv.z + pv.z*(1.f/3.f), hv.w + pv.w*(1.f/3.f));
        vb = *(const float4*)(Bm + (size_t)gc*Dm + lc);
    }
    As[0][lc+0][lr]=va.x; As[0][lc+1][lr]=va.y; As[0][lc+2][lr]=va.z; As[0][lc+3][lr]=va.w;
    Bs[0][lc+0][lr]=vb.x; Bs[0][lc+1][lr]=vb.y; Bs[0][lc+2][lr]=vb.z; Bs[0][lc+3][lr]=vb.w;
    __syncthreads();
    float acc[4][4] = {};
    #pragma unroll
    for (int s = 0; s < 8; s++) {
        int cur = s & 1;
        if (s < 7) {
            float4 hv = *(const float4*)(Arow + (s+1)*16 + lc);
            float4 pv = *(const float4*)(Prow + (s+1)*16 + lc);
            va = make_float4(hv.x + pv.x*(1.f/3.f), hv.y + pv.y*(1.f/3.f),
                             hv.z + pv.z*(1.f/3.f), hv.w + pv.w*(1.f/3.f));
            vb = *(const float4*)(Bm + (size_t)gc*Dm + (s+1)*16 + lc);
        }
        #pragma unroll
        for (int k = 0; k < 16; k++) {
            float4 a4 = *(const float4*)&As[cur][k][tr*4];
            float4 b4 = *(const float4*)&Bs[cur][k][tc*4];
            float a[4] = {a4.x, a4.y, a4.z, a4.w};
            float bv[4] = {b4.x, b4.y, b4.z, b4.w};
            #pragma unroll
            for (int i = 0; i < 4; i++)
                #pragma unroll
                for (int j = 0; j < 4; j++) acc[i][j] += a[i]*bv[j];
        }
        if (s < 7) {
            int nxt = cur ^ 1;
            As[nxt][lc+0][lr]=va.x; As[nxt][lc+1][lr]=va.y; As[nxt][lc+2][lr]=va.z; As[nxt][lc+3][lr]=va.w;
            Bs[nxt][lc+0][lr]=vb.x; Bs[nxt][lc+1][lr]=vb.y; Bs[nxt][lc+2][lr]=vb.z; Bs[nxt][lc+3][lr]=vb.w;
            __syncthreads();
        }
    }
    int c = c0 + tc*4;
    float4 bz = *(const float4*)(bias + c);
    #pragma unroll
    for (int i = 0; i < 4; i++) {
        int r = r0 + tr*4 + i;
        *(float4*)(out + (size_t)r*Dm + c) =
            make_float4(acc[i][0]+bz.x, acc[i][1]+bz.y, acc[i][2]+bz.z, acc[i][3]+bz.w);
    }
}

// ------------------------- host driver ---------------------------------------
extern "C" void kernel_launch(void* const* d_in, const int* in_sizes, int n_in,
                              void* d_out, int out_size)
{
    const float* coords = (const float*)d_in[0];
    const float* in_W   = (const float*)d_in[1];
    const float* in_b   = (const float*)d_in[2];
    const float* gnode  = (const float*)d_in[3];
    const float* Wq     = (const float*)d_in[4];
    const float* Wk     = (const float*)d_in[5];
    const float* Wv     = (const float*)d_in[6];
    const float* Wo     = (const float*)d_in[7];
    const float* emb    = (const float*)d_in[8];
    const float* W1     = (const float*)d_in[9];
    const float* b1     = (const float*)d_in[10];
    const float* W2     = (const float*)d_in[11];
    const float* b2     = (const float*)d_in[12];
    const float* n1w    = (const float*)d_in[13];
    const float* n1b    = (const float*)d_in[14];
    const float* n2w    = (const float*)d_in[15];
    const float* n2b    = (const float*)d_in[16];
    const float* outW   = (const float*)d_in[17];
    const float* outb   = (const float*)d_in[18];
    float* out = (float*)d_out;

    float *HG, *Y, *T1, *T2;
    cudaGetSymbolAddress((void**)&HG,  d_HG);
    cudaGetSymbolAddress((void**)&Y,   d_Y);
    cudaGetSymbolAddress((void**)&T1,  d_T1);
    cudaGetSymbolAddress((void**)&T2,  d_T2);

    const int Mall = Bsz*N1;  // 2050

    k_input<<<(Bsz*N1*Dm + 255)/256, 256>>>(coords, in_W, in_b, gnode);
    k_colmean<<<Bsz, 1024>>>();                            // layer-0 g update

    for (int l = 0; l < 3; l++) {
        k_par1<<<983, 256>>>(Wq + (size_t)l*Dm*Dm, Wk + (size_t)l*Dm*Dm, Wv + (size_t)l*Dm*Dm);
        k_par2<<<769, 256>>>(emb + (size_t)l*NBk*Dm);
        { dim3 ga(25, Hh, Bsz); k_attn<<<ga, 128>>>(coords); }

        { dim3 gq(Dm/64, NYT);
          k_gemmC<<<gq, 256>>>(Wo + (size_t)l*Dm*Dm, Y); }
        { dim3 g1(Dff/64, (Mall + 63)/64);
          k_gemmW1<<<g1, 256>>>(W1 + (size_t)l*Dff*Dm, b1 + l*Dff, n1w + l*Dm, n1b + l*Dm, T1); }
        { dim3 g2(Dm/64, NYT);
          k_gemmW2<<<g2, 256>>>(W2 + (size_t)l*Dm*Dff, b2 + l*Dm, n1w + l*Dm, n1b + l*Dm, T2); }
        { dim3 gi(Bsz, 4, 8); k_iapply<<<gi, 1024>>>(T2, HG, n2w + l*Dm, n2b + l*Dm); }
    }

    { dim3 ge(Dm/64, (Bsz*Nn)/64); k_fgemm<<<ge, 256>>>(outW, outb, out); }
}